// round 3
// baseline (speedup 1.0000x reference)
#include <cuda_runtime.h>
#include <math.h>

// Net_ASAP fused pipeline, round 2.
// - One CTA per graph (G=512), 512 threads, ~207KB dynamic smem.
// - Packed f32x2 FMA (Blackwell) in all dense GEMMs.
// - float4-vectorized smem GEMM operands; weights pre-transposed into a
//   __device__ global by a prologue kernel (conflict-free float4 staging).
// - Zero-skip on adjacency-operand GEMMs (~75% sparse).
// - Warp-parallel dots / argmax-topk / reductions for all small stages.

#define THREADS 512
#define G_TOT 512
#define SLOPE 0.2f
#define LDA 128
#define LDJ 68
#define LDW 128

typedef unsigned long long u64;

__device__ float g_WT[12 * 128 * 128];   // pre-transposed weights W^T[f][h]

// ---------------------------------------------------------------------------
// packed f32x2 helpers
// ---------------------------------------------------------------------------
__device__ __forceinline__ u64 bcast2(float v) {
  unsigned r = __float_as_uint(v);
  u64 d;
  asm("mov.b64 %0, {%1, %1};" : "=l"(d) : "r"(r));
  return d;
}
__device__ __forceinline__ u64 ffma2(u64 a, u64 b, u64 c) {
  u64 d;
  asm("fma.rn.f32x2 %0, %1, %2, %3;" : "=l"(d) : "l"(a), "l"(b), "l"(c));
  return d;
}
__device__ __forceinline__ u64 fmul2(u64 a, u64 b) {
  u64 d;
  asm("mul.rn.f32x2 %0, %1, %2;" : "=l"(d) : "l"(a), "l"(b));
  return d;
}

union V4 { float4 f; u64 p[2]; float s[4]; };

struct Smem {
  float A[64 * LDA];
  float B[64 * LDA];
  float Cb[64 * LDA];
  float ADJ[64 * LDJ];
  float S[64 * LDJ];
  float WT[128 * LDW];
  float part[512];
  float cnt[64], degw[64], s1[64], s2[64], fit[64];
  float av[64], bv[64], cv[64], vals[64];
  int   perm[64];
  float xsum[640];
  float adjn[256];
  float zz[128];
  float yy[16];
  float lse;
};

// ---------------------------------------------------------------------------
// GEMM core: acc[r][p] accumulates f32x2 pairs of
//   sum_k L[(i0+r)*ldl + k] * R[k*ldr + col]   cols = c0..c0+3, c0+64..c0+67
// SKIPZ: skip k when all row multipliers are zero (adjacency operands).
// ---------------------------------------------------------------------------
template<int RI, bool SKIPZ>
__device__ __forceinline__ void mm2(u64 (&acc)[RI][4],
    const float* __restrict__ L, int ldl,
    const float* __restrict__ R, int ldr,
    int i0, int c0, int K)
{
#pragma unroll 2
  for (int k = 0; k < K; k += 4) {
    V4 lv[RI];
#pragma unroll
    for (int r = 0; r < RI; r++)
      lv[r].f = *reinterpret_cast<const float4*>(L + (i0 + r) * ldl + k);
    const float* Rp = R + k * ldr + c0;
#pragma unroll
    for (int q = 0; q < 4; q++) {
      float l0 = lv[0].s[q];
      float l1 = 0.f;
      if constexpr (RI > 1) l1 = lv[1].s[q];
      if (SKIPZ) {
        bool any = (l0 != 0.f);
        if constexpr (RI > 1) any = any || (l1 != 0.f);
        if (!any) continue;
      }
      V4 ra, rb;
      ra.f = *reinterpret_cast<const float4*>(Rp + q * ldr);
      rb.f = *reinterpret_cast<const float4*>(Rp + q * ldr + 64);
      if (!SKIPZ || l0 != 0.f) {
        u64 lp = bcast2(l0);
        acc[0][0] = ffma2(lp, ra.p[0], acc[0][0]);
        acc[0][1] = ffma2(lp, ra.p[1], acc[0][1]);
        acc[0][2] = ffma2(lp, rb.p[0], acc[0][2]);
        acc[0][3] = ffma2(lp, rb.p[1], acc[0][3]);
      }
      if constexpr (RI > 1) {
        if (!SKIPZ || l1 != 0.f) {
          u64 lp = bcast2(l1);
          acc[1][0] = ffma2(lp, ra.p[0], acc[1][0]);
          acc[1][1] = ffma2(lp, ra.p[1], acc[1][1]);
          acc[1][2] = ffma2(lp, rb.p[0], acc[1][2]);
          acc[1][3] = ffma2(lp, rb.p[1], acc[1][3]);
        }
      }
    }
  }
}

template<int RI>
__device__ __forceinline__ void mm_zero(u64 (&acc)[RI][4]) {
#pragma unroll
  for (int r = 0; r < RI; r++)
#pragma unroll
    for (int j = 0; j < 4; j++) acc[r][j] = 0ull;
}

template<int RI>
__device__ __forceinline__ void mm_store(const u64 (&acc)[RI][4],
    float* O, int ldo, int i0, int c0)
{
#pragma unroll
  for (int r = 0; r < RI; r++) {
    V4 a, b;
    a.p[0] = acc[r][0]; a.p[1] = acc[r][1];
    b.p[0] = acc[r][2]; b.p[1] = acc[r][3];
    *reinterpret_cast<float4*>(O + (i0 + r) * ldo + c0)      = a.f;
    *reinterpret_cast<float4*>(O + (i0 + r) * ldo + c0 + 64) = b.f;
  }
}

// epilogue: (+bias, relu) then store
template<int RI, bool RELU>
__device__ __forceinline__ void mm_epi_store(const u64 (&acc)[RI][4],
    const float4 b1, const float4 b2, float* O, int ldo, int i0, int c0)
{
#pragma unroll
  for (int r = 0; r < RI; r++) {
    V4 a, b;
    a.p[0] = acc[r][0]; a.p[1] = acc[r][1];
    b.p[0] = acc[r][2]; b.p[1] = acc[r][3];
    a.f.x += b1.x; a.f.y += b1.y; a.f.z += b1.z; a.f.w += b1.w;
    b.f.x += b2.x; b.f.y += b2.y; b.f.z += b2.z; b.f.w += b2.w;
    if (RELU) {
      a.f.x = fmaxf(a.f.x, 0.f); a.f.y = fmaxf(a.f.y, 0.f);
      a.f.z = fmaxf(a.f.z, 0.f); a.f.w = fmaxf(a.f.w, 0.f);
      b.f.x = fmaxf(b.f.x, 0.f); b.f.y = fmaxf(b.f.y, 0.f);
      b.f.z = fmaxf(b.f.z, 0.f); b.f.w = fmaxf(b.f.w, 0.f);
    }
    *reinterpret_cast<float4*>(O + (i0 + r) * ldo + c0)      = a.f;
    *reinterpret_cast<float4*>(O + (i0 + r) * ldo + c0 + 64) = b.f;
  }
}

// masked max aggregation (scalar fmax, branch-skips zero adj entries)
template<int RI>
__device__ __forceinline__ void mm_maxagg(float (&acc)[RI][8],
    const float* __restrict__ Adj, const float* __restrict__ X,
    int i0, int c0, int NI)
{
#pragma unroll
  for (int r = 0; r < RI; r++)
#pragma unroll
    for (int c = 0; c < 8; c++) acc[r][c] = -1e30f;
  for (int k = 0; k < NI; k += 4) {
    V4 av[RI];
#pragma unroll
    for (int r = 0; r < RI; r++)
      av[r].f = *reinterpret_cast<const float4*>(Adj + (i0 + r) * LDJ + k);
#pragma unroll
    for (int q = 0; q < 4; q++) {
      bool any = (av[0].s[q] != 0.f);
      if constexpr (RI > 1) any = any || (av[1].s[q] != 0.f);
      if (!any) continue;
      V4 ra, rb;
      ra.f = *reinterpret_cast<const float4*>(X + (k + q) * LDA + c0);
      rb.f = *reinterpret_cast<const float4*>(X + (k + q) * LDA + c0 + 64);
#pragma unroll
      for (int r = 0; r < RI; r++) {
        float m = (r == 0) ? av[0].s[q] : av[RI - 1].s[q];
        if (m != 0.f) {
          acc[r][0] = fmaxf(acc[r][0], ra.s[0]);
          acc[r][1] = fmaxf(acc[r][1], ra.s[1]);
          acc[r][2] = fmaxf(acc[r][2], ra.s[2]);
          acc[r][3] = fmaxf(acc[r][3], ra.s[3]);
          acc[r][4] = fmaxf(acc[r][4], rb.s[0]);
          acc[r][5] = fmaxf(acc[r][5], rb.s[1]);
          acc[r][6] = fmaxf(acc[r][6], rb.s[2]);
          acc[r][7] = fmaxf(acc[r][7], rb.s[3]);
        }
      }
    }
  }
}

// ---------------------------------------------------------------------------
// small helpers
// ---------------------------------------------------------------------------
__device__ __forceinline__ void load_wt(float* WT, int widx, int tid) {
  const float4* src = reinterpret_cast<const float4*>(g_WT + widx * 16384);
  float4* dst = reinterpret_cast<float4*>(WT);
#pragma unroll
  for (int i = 0; i < 8; i++) dst[tid + i * 512] = src[tid + i * 512];
}

__device__ __forceinline__ float warp_red_sum(float v) {
#pragma unroll
  for (int o = 16; o; o >>= 1) v += __shfl_xor_sync(0xffffffffu, v, o);
  return v;
}

// ---------------------------------------------------------------------------
// graph conv: out = relu( ADJ @ (X @ wr^T) / cnt + X @ wroot^T + br )
// ---------------------------------------------------------------------------
template<int NI>
__device__ void graph_conv(Smem* s, float** Xp, float** T1p, float** T2p,
    int widx_r, int widx_root, const float* __restrict__ br, int tid)
{
  float* X  = *Xp;
  float* T1 = *T1p;
  float* T2 = *T2p;
  constexpr int RI = (NI == 64) ? 2 : 1;
  const int ti = tid >> 4, th = tid & 15, c0 = th * 4;
  const int i0 = (NI == 64) ? ti * 2 : ti;
  const bool act = (NI == 64) || (ti < NI);

  if (tid < NI) {
    const float* row = s->ADJ + tid * LDJ;
    int c = 0;
    for (int j = 0; j < NI; j++) c += (row[j] != 0.f) ? 1 : 0;
    s->cnt[tid] = (c > 0) ? (float)c : 1.f;
  }
  load_wt(s->WT, widx_r, tid);
  __syncthreads();

  u64 acc[RI][4];
  if (act) {
    mm_zero<RI>(acc);
    mm2<RI, false>(acc, X, LDA, s->WT, LDW, i0, c0, 128);
    mm_store<RI>(acc, T1, LDA, i0, c0);
  }
  __syncthreads();
  load_wt(s->WT, widx_root, tid);
  __syncthreads();

  if (act) {
    mm_zero<RI>(acc);
    mm2<RI, true>(acc, s->ADJ, LDJ, T1, LDA, i0, c0, NI);
#pragma unroll
    for (int r = 0; r < RI; r++) {
      u64 rp = bcast2(1.f / s->cnt[i0 + r]);
#pragma unroll
      for (int j = 0; j < 4; j++) acc[r][j] = fmul2(acc[r][j], rp);
    }
    mm2<RI, false>(acc, X, LDA, s->WT, LDW, i0, c0, 128);
    float4 b1 = *reinterpret_cast<const float4*>(br + c0);
    float4 b2 = *reinterpret_cast<const float4*>(br + c0 + 64);
    mm_epi_store<RI, true>(acc, b1, b2, T2, LDA, i0, c0);
  }
  __syncthreads();

  *Xp = T2; *T2p = X;   // features now in T2; old X becomes scratch
}

template<int NI>
__device__ void mean_pool(Smem* s, const float* X, int stage, int tid) {
  const int q = tid >> 7, h = tid & 127;
  float a = 0.f;
  for (int r = q; r < NI; r += 4) a += X[r * LDA + h];
  s->part[q * 128 + h] = a;
  __syncthreads();
  if (tid < 128)
    s->xsum[stage * 128 + tid] =
        (s->part[tid] + s->part[128 + tid] + s->part[256 + tid] + s->part[384 + tid])
        * (1.f / (float)NI);
  __syncthreads();
}

// ---------------------------------------------------------------------------
// ASAP pool
// ---------------------------------------------------------------------------
template<int NI, int KK>
__device__ void asap_pool(Smem* s, float** Xp, float** T1p, float** T2p,
    int widx_lin,
    const float* __restrict__ lb,
    const float* __restrict__ aw,  const float* __restrict__ abp,
    const float* __restrict__ l1w, const float* __restrict__ l1bp,
    const float* __restrict__ l2w,
    const float* __restrict__ l3w, const float* __restrict__ l3bp,
    int tid)
{
  float* X  = *Xp;
  float* T1 = *T1p;
  float* T2 = *T2p;
  constexpr int RI = (NI == 64) ? 2 : 1;
  const int ti = tid >> 4, th = tid & 15, c0 = th * 4;
  const int i0 = (NI == 64) ? ti * 2 : ti;
  const bool act = (NI == 64) || (ti < NI);
  const int w = tid >> 5, lane = tid & 31;
  const float ab = abp[0];

  // 1. adj1 diagonal fix
  if (tid < NI) {
    float d = s->ADJ[tid * LDJ + tid];
    if (d == 0.f) s->ADJ[tid * LDJ + tid] = 1.f;
  }
  __syncthreads();

  // 2. degw (warp row-sums) + masked max-agg -> T1 ; stage lw^T
  for (int d = w; d < NI; d += 16) {
    float a = 0.f;
    for (int j = lane; j < NI; j += 32) a += s->ADJ[d * LDJ + j];
    a = warp_red_sum(a);
    if (lane == 0) s->degw[d] = a;
  }
  if (act) {
    float mac[RI][8];
    mm_maxagg<RI>(mac, s->ADJ, X, i0, c0, NI);
#pragma unroll
    for (int r = 0; r < RI; r++) {
      *reinterpret_cast<float4*>(T1 + (i0 + r) * LDA + c0) =
          make_float4(mac[r][0], mac[r][1], mac[r][2], mac[r][3]);
      *reinterpret_cast<float4*>(T1 + (i0 + r) * LDA + c0 + 64) =
          make_float4(mac[r][4], mac[r][5], mac[r][6], mac[r][7]);
    }
  }
  load_wt(s->WT, widx_lin, tid);
  __syncthreads();

  // 3. XQ = T1 @ lw^T + lb -> T2
  if (act) {
    u64 acc[RI][4];
    mm_zero<RI>(acc);
    mm2<RI, false>(acc, T1, LDA, s->WT, LDW, i0, c0, 128);
    float4 b1 = *reinterpret_cast<const float4*>(lb + c0);
    float4 b2 = *reinterpret_cast<const float4*>(lb + c0 + 64);
    mm_epi_store<RI, false>(acc, b1, b2, T2, LDA, i0, c0);
  }
  __syncthreads();

  // 4. s1 = XQ . aw[:128], s2 = X . aw[128:]  (warp dots)
  for (int d = w; d < 2 * NI; d += 16) {
    const float* row = (d < NI) ? (T2 + d * LDA) : (X + (d - NI) * LDA);
    const float* wv  = (d < NI) ? aw : (aw + 128);
    float4 a = reinterpret_cast<const float4*>(row)[lane];
    float4 b = reinterpret_cast<const float4*>(wv)[lane];
    float dot = a.x * b.x + a.y * b.y + a.z * b.z + a.w * b.w;
    dot = warp_red_sum(dot);
    if (lane == 0) { if (d < NI) s->s1[d] = dot; else s->s2[d - NI] = dot; }
  }
  __syncthreads();

  // 5. masked softmax attention -> S
  {
    constexpr int NCH = (NI + 31) / 32;
    for (int i = w; i < NI; i += 16) {
      float s1i = s->s1[i];
      float ev[NCH];
      float mx = -1e30f;
#pragma unroll
      for (int c = 0; c < NCH; c++) {
        int j = c * 32 + lane;
        float adjv = (j < NI) ? s->ADJ[i * LDJ + j] : 0.f;
        float e = s1i + ((j < NI) ? s->s2[j] : 0.f) + ab;
        e = (e > 0.f) ? e : SLOPE * e;
        ev[c] = (adjv != 0.f) ? e : -1e30f;
        mx = fmaxf(mx, ev[c]);
      }
#pragma unroll
      for (int o = 16; o; o >>= 1) mx = fmaxf(mx, __shfl_xor_sync(0xffffffffu, mx, o));
      float sum = 0.f, ex[NCH];
#pragma unroll
      for (int c = 0; c < NCH; c++) {
        ex[c] = (ev[c] > -5e29f) ? __expf(ev[c] - mx) : 0.f;
        sum += ex[c];
      }
      sum = warp_red_sum(sum);
      float inv = 1.f / sum;
#pragma unroll
      for (int c = 0; c < NCH; c++) {
        int j = c * 32 + lane;
        if (j < NI) s->S[i * LDJ + j] = ex[c] * inv;
      }
    }
  }
  __syncthreads();

  // 6. XC = S @ X -> T1
  if (act) {
    u64 acc[RI][4];
    mm_zero<RI>(acc);
    mm2<RI, true>(acc, s->S, LDJ, X, LDA, i0, c0, NI);
    mm_store<RI>(acc, T1, LDA, i0, c0);
  }
  __syncthreads();

  // 7. av/bv/cv: three 128-dots per row of XC
  for (int d = w; d < 3 * NI; d += 16) {
    int grp = d / NI, i = d - grp * NI;
    const float* wv = (grp == 0) ? l1w : (grp == 1) ? l2w : l3w;
    float4 a = reinterpret_cast<const float4*>(T1 + i * LDA)[lane];
    float4 b = reinterpret_cast<const float4*>(wv)[lane];
    float dot = a.x * b.x + a.y * b.y + a.z * b.z + a.w * b.w;
    dot = warp_red_sum(dot);
    if (lane == 0) {
      if (grp == 0)      s->av[i] = dot + l1bp[0];
      else if (grp == 1) s->bv[i] = dot;
      else               s->cv[i] = dot + l3bp[0];
    }
  }
  __syncthreads();

  // 8. fit = sigmoid( adj1 @ av - bv*degw + cv )
  for (int d = w; d < NI; d += 16) {
    float a = 0.f;
    for (int j = lane; j < NI; j += 32) a += s->ADJ[d * LDJ + j] * s->av[j];
    a = warp_red_sum(a);
    if (lane == 0) {
      float f = a - s->bv[d] * s->degw[d] + s->cv[d];
      s->fit[d] = 1.f / (1.f + expf(-f));
    }
  }
  __syncthreads();

  // 9. top-k via warp argmax (warp 0); ties -> lowest index (matches top_k)
  if (tid < 32) {
    float v0 = (lane < NI) ? s->fit[lane] : -2.f;
    float v1 = (lane + 32 < NI) ? s->fit[lane + 32] : -2.f;
#pragma unroll 1
    for (int t = 0; t < KK; t++) {
      float bv; int bi;
      if (v0 >= v1) { bv = v0; bi = lane; } else { bv = v1; bi = lane + 32; }
#pragma unroll
      for (int o = 16; o; o >>= 1) {
        float ov = __shfl_xor_sync(0xffffffffu, bv, o);
        int   oi = __shfl_xor_sync(0xffffffffu, bi, o);
        if (ov > bv || (ov == bv && oi < bi)) { bv = ov; bi = oi; }
      }
      if (lane == 0) { s->perm[t] = bi; s->vals[t] = bv; }
      if (bi == lane) v0 = -2.f;
      if (bi == lane + 32) v1 = -2.f;
    }
  }
  __syncthreads();

  // 10. XN = XC[perm]*vals -> T2 ; Tb = S[perm] @ ADJ -> X (scratch)
  for (int idx = tid; idx < KK * 128; idx += THREADS) {
    int t = idx >> 7, h = idx & 127;
    T2[t * LDA + h] = T1[s->perm[t] * LDA + h] * s->vals[t];
  }
  for (int idx = tid; idx < KK * NI; idx += THREADS) {
    int t = idx / NI, m = idx - t * NI;
    const float* srow = s->S + s->perm[t] * LDJ;
    float a = 0.f;
    for (int n = 0; n < NI; n++) {
      float sv = srow[n];
      if (sv != 0.f) a += sv * s->ADJ[n * LDJ + m];
    }
    X[t * LDA + m] = a;
  }
  __syncthreads();

  // 11. adjn = Tb @ S[perm]^T, zero diagonal
  for (int idx = tid; idx < KK * KK; idx += THREADS) {
    int t = idx / KK, l = idx - t * KK;
    const float* sl = s->S + s->perm[l] * LDJ;
    const float* tr = X + t * LDA;
    float a = 0.f;
    for (int m = 0; m < NI; m++) a += tr[m] * sl[m];
    s->adjn[t * KK + l] = (t == l) ? 0.f : a;
  }
  __syncthreads();
  for (int idx = tid; idx < KK * KK; idx += THREADS) {
    int t = idx / KK, l = idx - t * KK;
    s->ADJ[t * LDJ + l] = s->adjn[t * KK + l];
  }
  __syncthreads();

  *Xp = T2; *T2p = X;
}

// ---------------------------------------------------------------------------
// main kernel
// ---------------------------------------------------------------------------
__global__ void __launch_bounds__(THREADS, 1) asap_kernel(
    const float* __restrict__ x,          const float* __restrict__ adj,
    const float* __restrict__ conv1_br,
    const float* __restrict__ convs_br,
    const float* __restrict__ pool_lin_b,
    const float* __restrict__ pool_att_w, const float* __restrict__ pool_att_b,
    const float* __restrict__ pool_le1_w, const float* __restrict__ pool_le1_b,
    const float* __restrict__ pool_le2_w,
    const float* __restrict__ pool_le3_w, const float* __restrict__ pool_le3_b,
    const float* __restrict__ lin1_w,     const float* __restrict__ lin1_b,
    const float* __restrict__ lin2_w,     const float* __restrict__ lin2_b,
    float* __restrict__ out)
{
  extern __shared__ unsigned char smraw[];
  Smem* s = reinterpret_cast<Smem*>(smraw);
  const int g = blockIdx.x, tid = threadIdx.x;
  const int w = tid >> 5, lane = tid & 31;

  // load features + adjacency (float4)
  {
    const float4* xs = reinterpret_cast<const float4*>(x + g * (64 * 128));
    float4* xd = reinterpret_cast<float4*>(s->A);
#pragma unroll
    for (int i = 0; i < 4; i++) xd[tid + i * 512] = xs[tid + i * 512];
    const float4* as = reinterpret_cast<const float4*>(adj + g * (64 * 64));
    for (int idx = tid; idx < 64 * 16; idx += THREADS) {
      int row = idx >> 4, c = idx & 15;
      *reinterpret_cast<float4*>(s->ADJ + row * LDJ + c * 4) = as[idx];
    }
  }
  __syncthreads();

  float* X  = s->A;
  float* T1 = s->B;
  float* T2 = s->Cb;

  graph_conv<64>(s, &X, &T1, &T2, 0, 1, conv1_br, tid);
  mean_pool<64>(s, X, 0, tid);

  graph_conv<64>(s, &X, &T1, &T2, 2, 6, convs_br, tid);
  mean_pool<64>(s, X, 1, tid);
  asap_pool<64, 16>(s, &X, &T1, &T2, 10,
      pool_lin_b, pool_att_w, pool_att_b,
      pool_le1_w, pool_le1_b, pool_le2_w, pool_le3_w, pool_le3_b, tid);

  graph_conv<16>(s, &X, &T1, &T2, 3, 7, convs_br + 128, tid);
  mean_pool<16>(s, X, 2, tid);

  graph_conv<16>(s, &X, &T1, &T2, 4, 8, convs_br + 256, tid);
  mean_pool<16>(s, X, 3, tid);
  asap_pool<16, 4>(s, &X, &T1, &T2, 11,
      pool_lin_b + 128, pool_att_w + 256, pool_att_b + 1,
      pool_le1_w + 128, pool_le1_b + 1, pool_le2_w + 128,
      pool_le3_w + 128, pool_le3_b + 1, tid);

  graph_conv<4>(s, &X, &T1, &T2, 5, 9, convs_br + 384, tid);
  mean_pool<4>(s, X, 4, tid);

  // MLP head: zz = relu( xsum(640) @ lin1_w^T + lin1_b )   (warp dots)
  for (int d = w; d < 128; d += 16) {
    const float4* zr = reinterpret_cast<const float4*>(s->xsum);
    const float4* wr = reinterpret_cast<const float4*>(lin1_w + d * 640);
    float a = 0.f;
#pragma unroll
    for (int c = 0; c < 5; c++) {
      float4 zc = zr[lane + 32 * c];
      float4 wc = wr[lane + 32 * c];
      a += zc.x * wc.x + zc.y * wc.y + zc.z * wc.z + zc.w * wc.w;
    }
    a = warp_red_sum(a);
    if (lane == 0) s->zz[d] = fmaxf(a + lin1_b[d], 0.f);
  }
  __syncthreads();
  for (int d = w; d < 10; d += 16) {
    float4 zc = reinterpret_cast<const float4*>(s->zz)[lane];
    float4 wc = reinterpret_cast<const float4*>(lin2_w + d * 128)[lane];
    float a = zc.x * wc.x + zc.y * wc.y + zc.z * wc.z + zc.w * wc.w;
    a = warp_red_sum(a);
    if (lane == 0) s->yy[d] = a + lin2_b[d];
  }
  __syncthreads();
  if (tid == 0) {
    float mx = -1e30f;
    for (int c = 0; c < 10; c++) mx = fmaxf(mx, s->yy[c]);
    float sum = 0.f;
    for (int c = 0; c < 10; c++) sum += expf(s->yy[c] - mx);
    s->lse = mx + logf(sum);
  }
  __syncthreads();
  if (tid < 10) out[g * 10 + tid] = s->yy[tid] - s->lse;
}

// ---------------------------------------------------------------------------
// prologue: transpose the 12 [128x128] weight matrices into g_WT
// ---------------------------------------------------------------------------
__global__ void transpose_k(
    const float* __restrict__ conv1_wr, const float* __restrict__ conv1_wroot,
    const float* __restrict__ convs_wr, const float* __restrict__ convs_wroot,
    const float* __restrict__ pool_lin_w)
{
  __shared__ float t[32][33];
  int mat = blockIdx.y;
  int tile = blockIdx.x;
  int tx = tile & 3, ty = tile >> 2;
  const float* src =
      (mat == 0) ? conv1_wr :
      (mat == 1) ? conv1_wroot :
      (mat < 6)  ? convs_wr + (mat - 2) * 16384 :
      (mat < 10) ? convs_wroot + (mat - 6) * 16384 :
                   pool_lin_w + (mat - 10) * 16384;
#pragma unroll
  for (int r = threadIdx.y; r < 32; r += 8)
    t[r][threadIdx.x] = src[(ty * 32 + r) * 128 + tx * 32 + threadIdx.x];
  __syncthreads();
#pragma unroll
  for (int r = threadIdx.y; r < 32; r += 8)
    g_WT[mat * 16384 + (tx * 32 + r) * 128 + ty * 32 + threadIdx.x] = t[threadIdx.x][r];
}

// ---------------------------------------------------------------------------
// launch
// ---------------------------------------------------------------------------
extern "C" void kernel_launch(void* const* d_in, const int* in_sizes, int n_in,
                              void* d_out, int out_size)
{
  const float* x           = (const float*)d_in[0];
  const float* adj         = (const float*)d_in[1];
  const float* conv1_wr    = (const float*)d_in[2];
  const float* conv1_br    = (const float*)d_in[3];
  const float* conv1_wroot = (const float*)d_in[4];
  const float* convs_wr    = (const float*)d_in[5];
  const float* convs_br    = (const float*)d_in[6];
  const float* convs_wroot = (const float*)d_in[7];
  const float* pool_lin_w  = (const float*)d_in[8];
  const float* pool_lin_b  = (const float*)d_in[9];
  const float* pool_att_w  = (const float*)d_in[10];
  const float* pool_att_b  = (const float*)d_in[11];
  const float* pool_le1_w  = (const float*)d_in[12];
  const float* pool_le1_b  = (const float*)d_in[13];
  const float* pool_le2_w  = (const float*)d_in[14];
  const float* pool_le3_w  = (const float*)d_in[15];
  const float* pool_le3_b  = (const float*)d_in[16];
  const float* lin1_w      = (const float*)d_in[17];
  const float* lin1_b      = (const float*)d_in[18];
  const float* lin2_w      = (const float*)d_in[19];
  const float* lin2_b      = (const float*)d_in[20];
  float* out = (float*)d_out;

  transpose_k<<<dim3(16, 12), dim3(32, 8)>>>(
      conv1_wr, conv1_wroot, convs_wr, convs_wroot, pool_lin_w);

  cudaFuncSetAttribute(asap_kernel, cudaFuncAttributeMaxDynamicSharedMemorySize,
                       (int)sizeof(Smem));
  asap_kernel<<<G_TOT, THREADS, sizeof(Smem)>>>(
      x, adj, conv1_br, convs_br,
      pool_lin_b, pool_att_w, pool_att_b,
      pool_le1_w, pool_le1_b, pool_le2_w, pool_le3_w, pool_le3_b,
      lin1_w, lin1_b, lin2_w, lin2_b, out);
}

// round 4
// speedup vs baseline: 1.2387x; 1.2387x over previous
#include <cuda_runtime.h>
#include <math.h>

// Net_ASAP fused pipeline, round 4.
// - One CTA per graph (G=512), 512 threads.
// - 4x8 register tiles; conv's two weight GEMMs run concurrently on two
//   256-thread groups against double-buffered smem weights (cp.async).
// - N=64 adjacency as u64 bitmasks (input adj is binary); popc counts.
// - In-place feature updates: 2 feature buffers only.

#define THREADS 512
#define G_TOT 512
#define SLOPE 0.2f
#define LDA 132
#define LDS_ 68
#define LDP 17

typedef unsigned long long u64;

__device__ float g_WT[12 * 128 * 128];   // pre-transposed weights W^T[k][h]

// ---------------------------------------------------------------------------
// packed f32x2 helpers
// ---------------------------------------------------------------------------
__device__ __forceinline__ u64 bcast2(float v) {
  unsigned r = __float_as_uint(v);
  u64 d; asm("mov.b64 %0, {%1, %1};" : "=l"(d) : "r"(r));
  return d;
}
__device__ __forceinline__ u64 ffma2(u64 a, u64 b, u64 c) {
  u64 d; asm("fma.rn.f32x2 %0, %1, %2, %3;" : "=l"(d) : "l"(a), "l"(b), "l"(c));
  return d;
}
__device__ __forceinline__ u64 fadd2(u64 a, u64 b) {
  u64 d; asm("add.rn.f32x2 %0, %1, %2;" : "=l"(d) : "l"(a), "l"(b));
  return d;
}
__device__ __forceinline__ u64 fmul2(u64 a, u64 b) {
  u64 d; asm("mul.rn.f32x2 %0, %1, %2;" : "=l"(d) : "l"(a), "l"(b));
  return d;
}

union V4 { float4 f; u64 p[2]; float s[4]; };

struct Smem {
  float A[64 * LDA];        // features (in-place)
  float B[64 * LDA];        // agg / xq / xc scratch
  float WT0[128 * 128];     // weight buffer 0
  float WT1[128 * 128];     // weight buffer 1
  float S[64 * LDS_];       // attention matrix
  u64   masks[64];          // binary adjacency, N=64 phase
  float adjP[16 * LDP];     // pooled float adjacency, N<=16
  float part[512];
  float degw[64], s1[64], s2[64], fit[64];
  float av[64], bv[64], cv[64], vals[64];
  int   perm[64];
  float xsum[640];
  float zz[128], yy[16], lse;
};

// ---------------------------------------------------------------------------
// cp.async weight prefetch: one 64KB matrix, 8 x 16B per thread
// ---------------------------------------------------------------------------
__device__ __forceinline__ void prefetch_wt(float* dst, int widx) {
  unsigned saddr = (unsigned)__cvta_generic_to_shared(dst);
  const char* gsrc = (const char*)(g_WT + widx * 16384);
  int tid = threadIdx.x;
#pragma unroll
  for (int i = 0; i < 8; i++) {
    int o = (tid + i * 512) * 16;
    asm volatile("cp.async.cg.shared.global [%0], [%1], 16;"
                 :: "r"(saddr + o), "l"(gsrc + o));
  }
  asm volatile("cp.async.commit_group;");
}
#define CP_WAIT asm volatile("cp.async.wait_group 0;" ::: "memory")

// ---------------------------------------------------------------------------
// 4x8 GEMM core: acc += L[i0..i0+3][k0..k0+K) * W[k][c0..c0+3, c0+64..c0+67]
// ---------------------------------------------------------------------------
__device__ __forceinline__ void mm48(u64 (&acc)[4][4],
    const float* __restrict__ L, const float* __restrict__ W,
    int i0, int c0, int k0, int K)
{
  const float* Lp = L + i0 * LDA + k0;
  const float* Wp = W + k0 * 128 + c0;
#pragma unroll 2
  for (int k = 0; k < K; k += 4) {
    V4 lv[4];
#pragma unroll
    for (int r = 0; r < 4; r++)
      lv[r].f = *reinterpret_cast<const float4*>(Lp + r * LDA + k);
#pragma unroll
    for (int q = 0; q < 4; q++) {
      V4 ra, rb;
      ra.f = *reinterpret_cast<const float4*>(Wp + (k + q) * 128);
      rb.f = *reinterpret_cast<const float4*>(Wp + (k + q) * 128 + 64);
#pragma unroll
      for (int r = 0; r < 4; r++) {
        u64 lp = bcast2(lv[r].s[q]);
        acc[r][0] = ffma2(lp, ra.p[0], acc[r][0]);
        acc[r][1] = ffma2(lp, ra.p[1], acc[r][1]);
        acc[r][2] = ffma2(lp, rb.p[0], acc[r][2]);
        acc[r][3] = ffma2(lp, rb.p[1], acc[r][3]);
      }
    }
  }
}

__device__ __forceinline__ void acc_zero(u64 (&acc)[4][4]) {
#pragma unroll
  for (int r = 0; r < 4; r++)
#pragma unroll
    for (int j = 0; j < 4; j++) acc[r][j] = 0ull;
}

__device__ __forceinline__ void tile_store(const u64 (&acc)[4][4],
    float* O, int i0, int c0)
{
#pragma unroll
  for (int r = 0; r < 4; r++) {
    V4 a, b;
    a.p[0] = acc[r][0]; a.p[1] = acc[r][1];
    b.p[0] = acc[r][2]; b.p[1] = acc[r][3];
    *reinterpret_cast<float4*>(O + (i0 + r) * LDA + c0)      = a.f;
    *reinterpret_cast<float4*>(O + (i0 + r) * LDA + c0 + 64) = b.f;
  }
}

// O_tile = acc + P_tile + bias (optional relu)
template<bool RELU>
__device__ __forceinline__ void tile_combine(const u64 (&acc)[4][4],
    const float* __restrict__ P, float* __restrict__ O,
    int i0, int c0, const float* __restrict__ bias)
{
  float4 b1 = *reinterpret_cast<const float4*>(bias + c0);
  float4 b2 = *reinterpret_cast<const float4*>(bias + c0 + 64);
#pragma unroll
  for (int r = 0; r < 4; r++) {
    V4 a, b, o1, o2;
    a.p[0] = acc[r][0]; a.p[1] = acc[r][1];
    b.p[0] = acc[r][2]; b.p[1] = acc[r][3];
    o1.f = *reinterpret_cast<const float4*>(P + (i0 + r) * LDA + c0);
    o2.f = *reinterpret_cast<const float4*>(P + (i0 + r) * LDA + c0 + 64);
    a.f.x += o1.f.x + b1.x; a.f.y += o1.f.y + b1.y;
    a.f.z += o1.f.z + b1.z; a.f.w += o1.f.w + b1.w;
    b.f.x += o2.f.x + b2.x; b.f.y += o2.f.y + b2.y;
    b.f.z += o2.f.z + b2.z; b.f.w += o2.f.w + b2.w;
    if (RELU) {
      a.f.x = fmaxf(a.f.x, 0.f); a.f.y = fmaxf(a.f.y, 0.f);
      a.f.z = fmaxf(a.f.z, 0.f); a.f.w = fmaxf(a.f.w, 0.f);
      b.f.x = fmaxf(b.f.x, 0.f); b.f.y = fmaxf(b.f.y, 0.f);
      b.f.z = fmaxf(b.f.z, 0.f); b.f.w = fmaxf(b.f.w, 0.f);
    }
    *reinterpret_cast<float4*>(O + (i0 + r) * LDA + c0)      = a.f;
    *reinterpret_cast<float4*>(O + (i0 + r) * LDA + c0 + 64) = b.f;
  }
}

__device__ __forceinline__ float warp_red_sum(float v) {
#pragma unroll
  for (int o = 16; o; o >>= 1) v += __shfl_xor_sync(0xffffffffu, v, o);
  return v;
}

// ---------------------------------------------------------------------------
// conv, N=64 (bitmask adjacency): A = relu( (adj@A)/cnt @ Wr + A@Wroot + br )
// ---------------------------------------------------------------------------
__device__ void conv64(Smem* s, const float* __restrict__ br) {
  const int tid = threadIdx.x;
  // agg = (masks @ A)/cnt -> B  (512 threads, 2 rows x 8 cols, bit iteration)
  {
    const int ti = tid >> 4, th = tid & 15;
    const int i0 = ti * 2, c0 = th * 4;
    u64 m0 = s->masks[i0], m1 = s->masks[i0 + 1];
    u64 a0[4] = {0,0,0,0}, a1[4] = {0,0,0,0};
    u64 mm = m0 | m1;
    const float* Ap = s->A + c0;
    while (mm) {
      int j = __ffsll((long long)mm) - 1;
      mm &= mm - 1;
      V4 ra, rb;
      ra.f = *reinterpret_cast<const float4*>(Ap + j * LDA);
      rb.f = *reinterpret_cast<const float4*>(Ap + j * LDA + 64);
      if ((m0 >> j) & 1) {
        a0[0] = fadd2(a0[0], ra.p[0]); a0[1] = fadd2(a0[1], ra.p[1]);
        a0[2] = fadd2(a0[2], rb.p[0]); a0[3] = fadd2(a0[3], rb.p[1]);
      }
      if ((m1 >> j) & 1) {
        a1[0] = fadd2(a1[0], ra.p[0]); a1[1] = fadd2(a1[1], ra.p[1]);
        a1[2] = fadd2(a1[2], rb.p[0]); a1[3] = fadd2(a1[3], rb.p[1]);
      }
    }
    u64 r0 = bcast2(1.f / fmaxf((float)__popcll(m0), 1.f));
    u64 r1 = bcast2(1.f / fmaxf((float)__popcll(m1), 1.f));
    V4 o;
    o.p[0] = fmul2(a0[0], r0); o.p[1] = fmul2(a0[1], r0);
    *reinterpret_cast<float4*>(s->B + i0 * LDA + c0) = o.f;
    o.p[0] = fmul2(a0[2], r0); o.p[1] = fmul2(a0[3], r0);
    *reinterpret_cast<float4*>(s->B + i0 * LDA + c0 + 64) = o.f;
    o.p[0] = fmul2(a1[0], r1); o.p[1] = fmul2(a1[1], r1);
    *reinterpret_cast<float4*>(s->B + (i0 + 1) * LDA + c0) = o.f;
    o.p[0] = fmul2(a1[2], r1); o.p[1] = fmul2(a1[3], r1);
    *reinterpret_cast<float4*>(s->B + (i0 + 1) * LDA + c0 + 64) = o.f;
  }
  CP_WAIT;
  __syncthreads();

  // dual-group GEMM: g0 = agg@Wr (B, WT0), g1 = X@Wroot (A, WT1)
  const int g = tid >> 8, t = tid & 255;
  const int i0 = (t >> 4) * 4, c0 = (t & 15) * 4;
  u64 acc[4][4];
  acc_zero(acc);
  if (g == 0) mm48(acc, s->B, s->WT0, i0, c0, 0, 128);
  else        mm48(acc, s->A, s->WT1, i0, c0, 0, 128);
  __syncthreads();
  if (g == 1) tile_store(acc, s->B, i0, c0);     // B (agg) is dead now
  __syncthreads();
  if (g == 0) tile_combine<true>(acc, s->B, s->A, i0, c0, br);  // -> A in place
  __syncthreads();
}

// ---------------------------------------------------------------------------
// conv, N<=16 (float adjP)
// ---------------------------------------------------------------------------
template<int NI>
__device__ void conv_small(Smem* s, const float* __restrict__ br) {
  const int tid = threadIdx.x;
  if (tid < NI * 16) {
    int row = tid >> 4, c0 = (tid & 15) * 4;
    float a[8] = {0,0,0,0,0,0,0,0};
    int cnt = 0;
    for (int j = 0; j < NI; j++) {
      float v = s->adjP[row * LDP + j];
      if (v != 0.f) {
        cnt++;
        V4 ra, rb;
        ra.f = *reinterpret_cast<const float4*>(s->A + j * LDA + c0);
        rb.f = *reinterpret_cast<const float4*>(s->A + j * LDA + c0 + 64);
        a[0] = fmaf(v, ra.s[0], a[0]); a[1] = fmaf(v, ra.s[1], a[1]);
        a[2] = fmaf(v, ra.s[2], a[2]); a[3] = fmaf(v, ra.s[3], a[3]);
        a[4] = fmaf(v, rb.s[0], a[4]); a[5] = fmaf(v, rb.s[1], a[5]);
        a[6] = fmaf(v, rb.s[2], a[6]); a[7] = fmaf(v, rb.s[3], a[7]);
      }
    }
    float rc = 1.f / fmaxf((float)cnt, 1.f);
    *reinterpret_cast<float4*>(s->B + row * LDA + c0) =
        make_float4(a[0]*rc, a[1]*rc, a[2]*rc, a[3]*rc);
    *reinterpret_cast<float4*>(s->B + row * LDA + c0 + 64) =
        make_float4(a[4]*rc, a[5]*rc, a[6]*rc, a[7]*rc);
  }
  CP_WAIT;
  __syncthreads();

  const int g = tid >> 8, t = tid & 255;
  const int i0 = (t >> 4) * 4, c0 = (t & 15) * 4;
  const bool act = i0 < NI;
  u64 acc[4][4];
  acc_zero(acc);
  if (act) {
    if (g == 0) mm48(acc, s->B, s->WT0, i0, c0, 0, 128);
    else        mm48(acc, s->A, s->WT1, i0, c0, 0, 128);
  }
  __syncthreads();
  if (g == 1 && act) tile_store(acc, s->B, i0, c0);
  __syncthreads();
  if (g == 0 && act) tile_combine<true>(acc, s->B, s->A, i0, c0, br);
  __syncthreads();
}

// ---------------------------------------------------------------------------
// mean pool of A rows -> xsum[stage]
// ---------------------------------------------------------------------------
__device__ void mean_pool(Smem* s, int NI, int stage) {
  const int tid = threadIdx.x;
  int q = tid >> 7, h = tid & 127;
  float a = 0.f;
  for (int r = q; r < NI; r += 4) a += s->A[r * LDA + h];
  s->part[q * 128 + h] = a;
  __syncthreads();
  if (tid < 128)
    s->xsum[stage * 128 + tid] =
        (s->part[tid] + s->part[128 + tid] + s->part[256 + tid] + s->part[384 + tid])
        * (1.f / (float)NI);
  __syncthreads();
}

// ---------------------------------------------------------------------------
// top-k (warp 0) — matches jax top_k (lowest index on ties)
// ---------------------------------------------------------------------------
template<int KK>
__device__ void topk(Smem* s, int NI) {
  if (threadIdx.x < 32) {
    int lane = threadIdx.x;
    float v0 = (lane < NI) ? s->fit[lane] : -2.f;
    float v1 = (lane + 32 < NI) ? s->fit[lane + 32] : -2.f;
#pragma unroll 1
    for (int t = 0; t < KK; t++) {
      float bv; int bi;
      if (v0 >= v1) { bv = v0; bi = lane; } else { bv = v1; bi = lane + 32; }
#pragma unroll
      for (int o = 16; o; o >>= 1) {
        float ov = __shfl_xor_sync(0xffffffffu, bv, o);
        int   oi = __shfl_xor_sync(0xffffffffu, bi, o);
        if (ov > bv || (ov == bv && oi < bi)) { bv = ov; bi = oi; }
      }
      if (lane == 0) { s->perm[t] = bi; s->vals[t] = bv; }
      if (bi == lane) v0 = -2.f;
      if (bi == lane + 32) v1 = -2.f;
    }
  }
}

// ---------------------------------------------------------------------------
// ASAP pool 1 (N=64 -> 16, bitmask adjacency; lw^T expected in WT0)
// ---------------------------------------------------------------------------
__device__ void pool1(Smem* s,
    const float* __restrict__ lb, const float* __restrict__ aw, float ab,
    const float* __restrict__ l1w, float l1b,
    const float* __restrict__ l2w,
    const float* __restrict__ l3w, float l3b)
{
  const int tid = threadIdx.x;
  const int w = tid >> 5, lane = tid & 31;

  if (tid < 64) s->masks[tid] |= (1ull << tid);   // adj1 diagonal
  __syncthreads();
  if (tid < 64) s->degw[tid] = (float)__popcll(s->masks[tid]);

  // masked max-agg -> B (2 rows x 8 cols per thread)
  {
    const int ti = tid >> 4, th = tid & 15;
    const int i0 = ti * 2, c0 = th * 4;
    u64 m0 = s->masks[i0], m1 = s->masks[i0 + 1];
    float a0[8], a1[8];
#pragma unroll
    for (int c = 0; c < 8; c++) { a0[c] = -1e30f; a1[c] = -1e30f; }
    u64 mm = m0 | m1;
    const float* Ap = s->A + c0;
    while (mm) {
      int j = __ffsll((long long)mm) - 1;
      mm &= mm - 1;
      V4 ra, rb;
      ra.f = *reinterpret_cast<const float4*>(Ap + j * LDA);
      rb.f = *reinterpret_cast<const float4*>(Ap + j * LDA + 64);
      if ((m0 >> j) & 1) {
        a0[0]=fmaxf(a0[0],ra.s[0]); a0[1]=fmaxf(a0[1],ra.s[1]);
        a0[2]=fmaxf(a0[2],ra.s[2]); a0[3]=fmaxf(a0[3],ra.s[3]);
        a0[4]=fmaxf(a0[4],rb.s[0]); a0[5]=fmaxf(a0[5],rb.s[1]);
        a0[6]=fmaxf(a0[6],rb.s[2]); a0[7]=fmaxf(a0[7],rb.s[3]);
      }
      if ((m1 >> j) & 1) {
        a1[0]=fmaxf(a1[0],ra.s[0]); a1[1]=fmaxf(a1[1],ra.s[1]);
        a1[2]=fmaxf(a1[2],ra.s[2]); a1[3]=fmaxf(a1[3],ra.s[3]);
        a1[4]=fmaxf(a1[4],rb.s[0]); a1[5]=fmaxf(a1[5],rb.s[1]);
        a1[6]=fmaxf(a1[6],rb.s[2]); a1[7]=fmaxf(a1[7],rb.s[3]);
      }
    }
    *reinterpret_cast<float4*>(s->B + i0*LDA + c0) = make_float4(a0[0],a0[1],a0[2],a0[3]);
    *reinterpret_cast<float4*>(s->B + i0*LDA + c0 + 64) = make_float4(a0[4],a0[5],a0[6],a0[7]);
    *reinterpret_cast<float4*>(s->B + (i0+1)*LDA + c0) = make_float4(a1[0],a1[1],a1[2],a1[3]);
    *reinterpret_cast<float4*>(s->B + (i0+1)*LDA + c0 + 64) = make_float4(a1[4],a1[5],a1[6],a1[7]);
  }
  CP_WAIT;
  __syncthreads();

  // XQ = B @ lw^T + lb -> B  (K-split dual group)
  {
    const int g = tid >> 8, t = tid & 255;
    const int i0 = (t >> 4) * 4, c0 = (t & 15) * 4;
    u64 acc[4][4];
    acc_zero(acc);
    mm48(acc, s->B, s->WT0, i0, c0, g ? 64 : 0, 64);
    __syncthreads();
    if (g == 1) tile_store(acc, s->B, i0, c0);
    __syncthreads();
    if (g == 0) tile_combine<false>(acc, s->B, s->B, i0, c0, lb);
  }
  __syncthreads();

  // s1 = XQ.aw[:128] (B), s2 = X.aw[128:] (A)
  for (int d = w; d < 128; d += 16) {
    const float* row = (d < 64) ? (s->B + d * LDA) : (s->A + (d - 64) * LDA);
    const float* wv = (d < 64) ? aw : (aw + 128);
    float4 a = reinterpret_cast<const float4*>(row)[lane];
    float4 b = reinterpret_cast<const float4*>(wv)[lane];
    float dot = warp_red_sum(a.x*b.x + a.y*b.y + a.z*b.z + a.w*b.w);
    if (lane == 0) { if (d < 64) s->s1[d] = dot; else s->s2[d - 64] = dot; }
  }
  __syncthreads();

  // masked softmax attention -> S (full 64 cols written; 0 where unmasked)
  for (int i = w; i < 64; i += 16) {
    u64 mi = s->masks[i];
    float s1i = s->s1[i];
    bool vA = (mi >> lane) & 1, vB = (mi >> (lane + 32)) & 1;
    float e0 = s1i + s->s2[lane] + ab;       e0 = (e0 > 0.f) ? e0 : SLOPE * e0;
    float e1 = s1i + s->s2[lane + 32] + ab;  e1 = (e1 > 0.f) ? e1 : SLOPE * e1;
    float ev0 = vA ? e0 : -1e30f, ev1 = vB ? e1 : -1e30f;
    float mx = fmaxf(ev0, ev1);
#pragma unroll
    for (int o = 16; o; o >>= 1) mx = fmaxf(mx, __shfl_xor_sync(0xffffffffu, mx, o));
    float ex0 = vA ? __expf(ev0 - mx) : 0.f;
    float ex1 = vB ? __expf(ev1 - mx) : 0.f;
    float sum = warp_red_sum(ex0 + ex1);
    float inv = 1.f / sum;
    s->S[i * LDS_ + lane]      = ex0 * inv;
    s->S[i * LDS_ + lane + 32] = ex1 * inv;
  }
  __syncthreads();

  // XC = S @ X -> B  (2x8 tiles, zero-skip)
  {
    const int ti = tid >> 4, th = tid & 15;
    const int i0 = ti * 2, c0 = th * 4;
    u64 a0[4] = {0,0,0,0}, a1[4] = {0,0,0,0};
    for (int k = 0; k < 64; k++) {
      float l0 = s->S[i0 * LDS_ + k], l1 = s->S[(i0 + 1) * LDS_ + k];
      if (l0 == 0.f && l1 == 0.f) continue;
      V4 ra, rb;
      ra.f = *reinterpret_cast<const float4*>(s->A + k * LDA + c0);
      rb.f = *reinterpret_cast<const float4*>(s->A + k * LDA + c0 + 64);
      if (l0 != 0.f) {
        u64 lp = bcast2(l0);
        a0[0]=ffma2(lp,ra.p[0],a0[0]); a0[1]=ffma2(lp,ra.p[1],a0[1]);
        a0[2]=ffma2(lp,rb.p[0],a0[2]); a0[3]=ffma2(lp,rb.p[1],a0[3]);
      }
      if (l1 != 0.f) {
        u64 lp = bcast2(l1);
        a1[0]=ffma2(lp,ra.p[0],a1[0]); a1[1]=ffma2(lp,ra.p[1],a1[1]);
        a1[2]=ffma2(lp,rb.p[0],a1[2]); a1[3]=ffma2(lp,rb.p[1],a1[3]);
      }
    }
    V4 o;
    o.p[0]=a0[0]; o.p[1]=a0[1]; *reinterpret_cast<float4*>(s->B + i0*LDA + c0) = o.f;
    o.p[0]=a0[2]; o.p[1]=a0[3]; *reinterpret_cast<float4*>(s->B + i0*LDA + c0 + 64) = o.f;
    o.p[0]=a1[0]; o.p[1]=a1[1]; *reinterpret_cast<float4*>(s->B + (i0+1)*LDA + c0) = o.f;
    o.p[0]=a1[2]; o.p[1]=a1[3]; *reinterpret_cast<float4*>(s->B + (i0+1)*LDA + c0 + 64) = o.f;
  }
  __syncthreads();

  // av/bv/cv dots
  for (int d = w; d < 192; d += 16) {
    int grp = d >> 6, i = d & 63;
    const float* wv = (grp == 0) ? l1w : (grp == 1) ? l2w : l3w;
    float4 a = reinterpret_cast<const float4*>(s->B + i * LDA)[lane];
    float4 b = reinterpret_cast<const float4*>(wv)[lane];
    float dot = warp_red_sum(a.x*b.x + a.y*b.y + a.z*b.z + a.w*b.w);
    if (lane == 0) {
      if (grp == 0)      s->av[i] = dot + l1b;
      else if (grp == 1) s->bv[i] = dot;
      else               s->cv[i] = dot + l3b;
    }
  }
  __syncthreads();

  // fit = sigmoid( adj1@av - bv*degw + cv )
  if (tid < 64) {
    u64 mm = s->masks[tid];
    float a = 0.f;
    while (mm) {
      int j = __ffsll((long long)mm) - 1;
      mm &= mm - 1;
      a += s->av[j];
    }
    float f = a - s->bv[tid] * s->degw[tid] + s->cv[tid];
    s->fit[tid] = 1.f / (1.f + expf(-f));
  }
  __syncthreads();
  topk<16>(s, 64);
  __syncthreads();

  // XN = XC[perm]*vals -> A rows 0..15 ; T = S[perm]@adj1 -> A rows 16..31
  for (int idx = tid; idx < 16 * 128; idx += THREADS) {
    int t2 = idx >> 7, h = idx & 127;
    s->A[t2 * LDA + h] = s->B[s->perm[t2] * LDA + h] * s->vals[t2];
  }
  for (int idx = tid; idx < 16 * 64; idx += THREADS) {
    int t2 = idx >> 6, m = idx & 63;
    const float* srow = s->S + s->perm[t2] * LDS_;
    float a = 0.f;
    for (int n = 0; n < 64; n++) {
      float sv = srow[n];
      if (sv != 0.f && ((s->masks[n] >> m) & 1)) a += sv;
    }
    s->A[(16 + t2) * LDA + m] = a;
  }
  __syncthreads();

  // adjn = T @ S[perm]^T, zero diag -> adjP
  if (tid < 256) {
    int t2 = tid >> 4, l = tid & 15;
    const float* sl = s->S + s->perm[l] * LDS_;
    const float* tr = s->A + (16 + t2) * LDA;
    float a = 0.f;
    for (int m = 0; m < 64; m++) a += tr[m] * sl[m];
    s->adjP[t2 * LDP + l] = (t2 == l) ? 0.f : a;
  }
  __syncthreads();
}

// ---------------------------------------------------------------------------
// ASAP pool 2 (N=16 -> 4, float adjP; lw^T expected in WT0)
// ---------------------------------------------------------------------------
__device__ void pool2(Smem* s,
    const float* __restrict__ lb, const float* __restrict__ aw, float ab,
    const float* __restrict__ l1w, float l1b,
    const float* __restrict__ l2w,
    const float* __restrict__ l3w, float l3b)
{
  const int tid = threadIdx.x;
  const int w = tid >> 5, lane = tid & 31;

  if (tid < 16) {
    float d = s->adjP[tid * LDP + tid];
    if (d == 0.f) s->adjP[tid * LDP + tid] = 1.f;
  }
  __syncthreads();
  if (tid < 16) {
    float sum = 0.f;
    for (int j = 0; j < 16; j++) sum += s->adjP[tid * LDP + j];
    s->degw[tid] = sum;
  }

  // masked max-agg -> B
  if (tid < 256) {
    int row = tid >> 4, c0 = (tid & 15) * 4;
    float a[8];
#pragma unroll
    for (int c = 0; c < 8; c++) a[c] = -1e30f;
    for (int j = 0; j < 16; j++) {
      if (s->adjP[row * LDP + j] != 0.f) {
        V4 ra, rb;
        ra.f = *reinterpret_cast<const float4*>(s->A + j * LDA + c0);
        rb.f = *reinterpret_cast<const float4*>(s->A + j * LDA + c0 + 64);
        a[0]=fmaxf(a[0],ra.s[0]); a[1]=fmaxf(a[1],ra.s[1]);
        a[2]=fmaxf(a[2],ra.s[2]); a[3]=fmaxf(a[3],ra.s[3]);
        a[4]=fmaxf(a[4],rb.s[0]); a[5]=fmaxf(a[5],rb.s[1]);
        a[6]=fmaxf(a[6],rb.s[2]); a[7]=fmaxf(a[7],rb.s[3]);
      }
    }
    *reinterpret_cast<float4*>(s->B + row*LDA + c0) = make_float4(a[0],a[1],a[2],a[3]);
    *reinterpret_cast<float4*>(s->B + row*LDA + c0 + 64) = make_float4(a[4],a[5],a[6],a[7]);
  }
  CP_WAIT;
  __syncthreads();

  // XQ = B @ lw^T + lb -> B  (K-split dual group, 16 rows)
  {
    const int g = tid >> 8, t = tid & 255;
    const int i0 = (t >> 4) * 4, c0 = (t & 15) * 4;
    const bool act = i0 < 16;
    u64 acc[4][4];
    acc_zero(acc);
    if (act) mm48(acc, s->B, s->WT0, i0, c0, g ? 64 : 0, 64);
    __syncthreads();
    if (g == 1 && act) tile_store(acc, s->B, i0, c0);
    __syncthreads();
    if (g == 0 && act) tile_combine<false>(acc, s->B, s->B, i0, c0, lb);
  }
  __syncthreads();

  // s1/s2
  for (int d = w; d < 32; d += 16) {
    const float* row = (d < 16) ? (s->B + d * LDA) : (s->A + (d - 16) * LDA);
    const float* wv = (d < 16) ? aw : (aw + 128);
    float4 a = reinterpret_cast<const float4*>(row)[lane];
    float4 b = reinterpret_cast<const float4*>(wv)[lane];
    float dot = warp_red_sum(a.x*b.x + a.y*b.y + a.z*b.z + a.w*b.w);
    if (lane == 0) { if (d < 16) s->s1[d] = dot; else s->s2[d - 16] = dot; }
  }
  __syncthreads();

  // attention (one warp per row, 16 rows)
  if (w < 16) {
    int i = w;
    float adjv = (lane < 16) ? s->adjP[i * LDP + lane] : 0.f;
    float e = s->s1[i] + ((lane < 16) ? s->s2[lane] : 0.f) + ab;
    e = (e > 0.f) ? e : SLOPE * e;
    float ev = (adjv != 0.f) ? e : -1e30f;
    float mx = ev;
#pragma unroll
    for (int o = 16; o; o >>= 1) mx = fmaxf(mx, __shfl_xor_sync(0xffffffffu, mx, o));
    float ex = (adjv != 0.f) ? __expf(ev - mx) : 0.f;
    float sum = warp_red_sum(ex);
    if (lane < 16) s->S[i * LDS_ + lane] = ex / sum;
  }
  __syncthreads();

  // XC = S @ X -> B
  if (tid < 256) {
    int row = tid >> 4, c0 = (tid & 15) * 4;
    float a[8] = {0,0,0,0,0,0,0,0};
    for (int j = 0; j < 16; j++) {
      float sv = s->S[row * LDS_ + j];
      if (sv != 0.f) {
        V4 ra, rb;
        ra.f = *reinterpret_cast<const float4*>(s->A + j * LDA + c0);
        rb.f = *reinterpret_cast<const float4*>(s->A + j * LDA + c0 + 64);
        a[0]=fmaf(sv,ra.s[0],a[0]); a[1]=fmaf(sv,ra.s[1],a[1]);
        a[2]=fmaf(sv,ra.s[2],a[2]); a[3]=fmaf(sv,ra.s[3],a[3]);
        a[4]=fmaf(sv,rb.s[0],a[4]); a[5]=fmaf(sv,rb.s[1],a[5]);
        a[6]=fmaf(sv,rb.s[2],a[6]); a[7]=fmaf(sv,rb.s[3],a[7]);
      }
    }
    *reinterpret_cast<float4*>(s->B + row*LDA + c0) = make_float4(a[0],a[1],a[2],a[3]);
    *reinterpret_cast<float4*>(s->B + row*LDA + c0 + 64) = make_float4(a[4],a[5],a[6],a[7]);
  }
  __syncthreads();

  // av/bv/cv
  for (int d = w; d < 48; d += 16) {
    int grp = d >> 4, i = d & 15;
    const float* wv = (grp == 0) ? l1w : (grp == 1) ? l2w : l3w;
    float4 a = reinterpret_cast<const float4*>(s->B + i * LDA)[lane];
    float4 b = reinterpret_cast<const float4*>(wv)[lane];
    float dot = warp_red_sum(a.x*b.x + a.y*b.y + a.z*b.z + a.w*b.w);
    if (lane == 0) {
      if (grp == 0)      s->av[i] = dot + l1b;
      else if (grp == 1) s->bv[i] = dot;
      else               s->cv[i] = dot + l3b;
    }
  }
  __syncthreads();

  if (tid < 16) {
    float a = 0.f;
    for (int j = 0; j < 16; j++) a += s->adjP[tid * LDP + j] * s->av[j];
    float f = a - s->bv[tid] * s->degw[tid] + s->cv[tid];
    s->fit[tid] = 1.f / (1.f + expf(-f));
  }
  __syncthreads();
  topk<4>(s, 16);
  __syncthreads();

  // XN -> A rows 0..3 ; T -> A rows 16..19
  {
    int t2 = tid >> 7, h = tid & 127;
    s->A[t2 * LDA + h] = s->B[s->perm[t2] * LDA + h] * s->vals[t2];
  }
  if (tid < 64) {
    int t2 = tid >> 4, m = tid & 15;
    const float* srow = s->S + s->perm[t2] * LDS_;
    float a = 0.f;
    for (int n = 0; n < 16; n++) a += srow[n] * s->adjP[n * LDP + m];
    s->A[(16 + t2) * LDA + m] = a;
  }
  __syncthreads();
  if (tid < 16) {
    int t2 = tid >> 2, l = tid & 3;
    const float* sl = s->S + s->perm[l] * LDS_;
    const float* tr = s->A + (16 + t2) * LDA;
    float a = 0.f;
    for (int m = 0; m < 16; m++) a += tr[m] * sl[m];
    s->adjP[t2 * LDP + l] = (t2 == l) ? 0.f : a;
  }
  __syncthreads();
}

// ---------------------------------------------------------------------------
// main kernel
// ---------------------------------------------------------------------------
__global__ void __launch_bounds__(THREADS, 1) asap_kernel(
    const float* __restrict__ x,          const float* __restrict__ adj,
    const float* __restrict__ conv1_br,
    const float* __restrict__ convs_br,
    const float* __restrict__ pool_lin_b,
    const float* __restrict__ pool_att_w, const float* __restrict__ pool_att_b,
    const float* __restrict__ pool_le1_w, const float* __restrict__ pool_le1_b,
    const float* __restrict__ pool_le2_w,
    const float* __restrict__ pool_le3_w, const float* __restrict__ pool_le3_b,
    const float* __restrict__ lin1_w,     const float* __restrict__ lin1_b,
    const float* __restrict__ lin2_w,     const float* __restrict__ lin2_b,
    float* __restrict__ out)
{
  extern __shared__ unsigned char smraw[];
  Smem* s = reinterpret_cast<Smem*>(smraw);
  const int g = blockIdx.x, tid = threadIdx.x;
  const int w = tid >> 5, lane = tid & 31;

  prefetch_wt(s->WT0, 0);
  prefetch_wt(s->WT1, 1);

  // load features (float4, re-strided to LDA) + binary adjacency -> masks
  {
    const float4* xs = reinterpret_cast<const float4*>(x + (size_t)g * 8192);
#pragma unroll
    for (int i = 0; i < 4; i++) {
      int idx = tid + i * 512;
      int row = idx >> 5, c = (idx & 31) * 4;
      *reinterpret_cast<float4*>(s->A + row * LDA + c) = xs[idx];
    }
    if (tid < 64) {
      const float4* ar = reinterpret_cast<const float4*>(adj + (size_t)g * 4096 + tid * 64);
      u64 m = 0;
#pragma unroll
      for (int c = 0; c < 16; c++) {
        float4 v = __ldg(ar + c);
        if (v.x != 0.f) m |= 1ull << (c * 4 + 0);
        if (v.y != 0.f) m |= 1ull << (c * 4 + 1);
        if (v.z != 0.f) m |= 1ull << (c * 4 + 2);
        if (v.w != 0.f) m |= 1ull << (c * 4 + 3);
      }
      s->masks[tid] = m;
    }
  }
  __syncthreads();

  conv64(s, conv1_br);                 // WT 0,1
  prefetch_wt(s->WT0, 2);
  prefetch_wt(s->WT1, 6);
  mean_pool(s, 64, 0);

  conv64(s, convs_br);                 // WT 2,6
  prefetch_wt(s->WT0, 10);
  mean_pool(s, 64, 1);

  pool1(s, pool_lin_b, pool_att_w, pool_att_b[0],
        pool_le1_w, pool_le1_b[0], pool_le2_w, pool_le3_w, pool_le3_b[0]);
  prefetch_wt(s->WT0, 3);
  prefetch_wt(s->WT1, 7);

  conv_small<16>(s, convs_br + 128);   // WT 3,7
  prefetch_wt(s->WT0, 4);
  prefetch_wt(s->WT1, 8);
  mean_pool(s, 16, 2);

  conv_small<16>(s, convs_br + 256);   // WT 4,8
  prefetch_wt(s->WT0, 11);
  mean_pool(s, 16, 3);

  pool2(s, pool_lin_b + 128, pool_att_w + 256, pool_att_b[1],
        pool_le1_w + 128, pool_le1_b[1], pool_le2_w + 128,
        pool_le3_w + 128, pool_le3_b[1]);
  prefetch_wt(s->WT0, 5);
  prefetch_wt(s->WT1, 9);

  conv_small<4>(s, convs_br + 384);    // WT 5,9
  mean_pool(s, 4, 4);

  // MLP head
  for (int d = w; d < 128; d += 16) {
    const float4* zr = reinterpret_cast<const float4*>(s->xsum);
    const float4* wr = reinterpret_cast<const float4*>(lin1_w + d * 640);
    float a = 0.f;
#pragma unroll
    for (int c = 0; c < 5; c++) {
      float4 zc = zr[lane + 32 * c];
      float4 wc = wr[lane + 32 * c];
      a += zc.x*wc.x + zc.y*wc.y + zc.z*wc.z + zc.w*wc.w;
    }
    a = warp_red_sum(a);
    if (lane == 0) s->zz[d] = fmaxf(a + lin1_b[d], 0.f);
  }
  __syncthreads();
  for (int d = w; d < 10; d += 16) {
    float4 zc = reinterpret_cast<const float4*>(s->zz)[lane];
    float4 wc = reinterpret_cast<const float4*>(lin2_w + d * 128)[lane];
    float a = warp_red_sum(zc.x*wc.x + zc.y*wc.y + zc.z*wc.z + zc.w*wc.w);
    if (lane == 0) s->yy[d] = a + lin2_b[d];
  }
  __syncthreads();
  if (tid == 0) {
    float mx = -1e30f;
    for (int c = 0; c < 10; c++) mx = fmaxf(mx, s->yy[c]);
    float sum = 0.f;
    for (int c = 0; c < 10; c++) sum += expf(s->yy[c] - mx);
    s->lse = mx + logf(sum);
  }
  __syncthreads();
  if (tid < 10) out[g * 10 + tid] = s->yy[tid] - s->lse;
}

// ---------------------------------------------------------------------------
// prologue: transpose the 12 [128x128] weight matrices into g_WT
// ---------------------------------------------------------------------------
__global__ void transpose_k(
    const float* __restrict__ conv1_wr, const float* __restrict__ conv1_wroot,
    const float* __restrict__ convs_wr, const float* __restrict__ convs_wroot,
    const float* __restrict__ pool_lin_w)
{
  __shared__ float t[32][33];
  int mat = blockIdx.y;
  int tile = blockIdx.x;
  int tx = tile & 3, ty = tile >> 2;
  const float* src =
      (mat == 0) ? conv1_wr :
      (mat == 1) ? conv1_wroot :
      (mat < 6)  ? convs_wr + (mat - 2) * 16384 :
      (mat < 10) ? convs_wroot + (mat - 6) * 16384 :
                   pool_lin_w + (mat - 10) * 16384;
#pragma unroll
  for (int r = threadIdx.y; r < 32; r += 8)
    t[r][threadIdx.x] = src[(ty * 32 + r) * 128 + tx * 32 + threadIdx.x];
  __syncthreads();
#pragma unroll
  for (int r = threadIdx.y; r < 32; r += 8)
    g_WT[mat * 16384 + (tx * 32 + r) * 128 + ty * 32 + threadIdx.x] = t[threadIdx.x][r];
}

// ---------------------------------------------------------------------------
// launch
// ---------------------------------------------------------------------------
extern "C" void kernel_launch(void* const* d_in, const int* in_sizes, int n_in,
                              void* d_out, int out_size)
{
  const float* x           = (const float*)d_in[0];
  const float* adj         = (const float*)d_in[1];
  const float* conv1_wr    = (const float*)d_in[2];
  const float* conv1_br    = (const float*)d_in[3];
  const float* conv1_wroot = (const float*)d_in[4];
  const float* convs_wr    = (const float*)d_in[5];
  const float* convs_br    = (const float*)d_in[6];
  const float* convs_wroot = (const float*)d_in[7];
  const float* pool_lin_w  = (const float*)d_in[8];
  const float* pool_lin_b  = (const float*)d_in[9];
  const float* pool_att_w  = (const float*)d_in[10];
  const float* pool_att_b  = (const float*)d_in[11];
  const float* pool_le1_w  = (const float*)d_in[12];
  const float* pool_le1_b  = (const float*)d_in[13];
  const float* pool_le2_w  = (const float*)d_in[14];
  const float* pool_le3_w  = (const float*)d_in[15];
  const float* pool_le3_b  = (const float*)d_in[16];
  const float* lin1_w      = (const float*)d_in[17];
  const float* lin1_b      = (const float*)d_in[18];
  const float* lin2_w      = (const float*)d_in[19];
  const float* lin2_b      = (const float*)d_in[20];
  float* out = (float*)d_out;

  transpose_k<<<dim3(16, 12), dim3(32, 8)>>>(
      conv1_wr, conv1_wroot, convs_wr, convs_wroot, pool_lin_w);

  cudaFuncSetAttribute(asap_kernel, cudaFuncAttributeMaxDynamicSharedMemorySize,
                       (int)sizeof(Smem));
  asap_kernel<<<G_TOT, THREADS, sizeof(Smem)>>>(
      x, adj, conv1_br, convs_br,
      pool_lin_b, pool_att_w, pool_att_b,
      pool_le1_w, pool_le1_b, pool_le2_w, pool_le3_w, pool_le3_b,
      lin1_w, lin1_b, lin2_w, lin2_b, out);
}

// round 5
// speedup vs baseline: 1.2621x; 1.0189x over previous
#include <cuda_runtime.h>
#include <math.h>

// Net_ASAP fused pipeline, round 5.
// - conv64 weight GEMMs: 8-row x 4-col register tiles, 4 column-split groups
//   (2 GEMMs x 2 col-halves) -> W smem reads amortized over 8 rows, warp-level
//   broadcast dedup on W rows => FFMA-bound instead of crossbar-contended.
// - Everything else retained from round 4 (bitmask adjacency, cp.async
//   double-buffered weights, warp-parallel small stages).

#define THREADS 512
#define G_TOT 512
#define SLOPE 0.2f
#define LDA 132
#define LDS_ 68
#define LDP 17

typedef unsigned long long u64;

__device__ float g_WT[12 * 128 * 128];   // pre-transposed weights W^T[k][h]

// ---------------------------------------------------------------------------
// packed f32x2 helpers
// ---------------------------------------------------------------------------
__device__ __forceinline__ u64 bcast2(float v) {
  unsigned r = __float_as_uint(v);
  u64 d; asm("mov.b64 %0, {%1, %1};" : "=l"(d) : "r"(r));
  return d;
}
__device__ __forceinline__ u64 ffma2(u64 a, u64 b, u64 c) {
  u64 d; asm("fma.rn.f32x2 %0, %1, %2, %3;" : "=l"(d) : "l"(a), "l"(b), "l"(c));
  return d;
}
__device__ __forceinline__ u64 fadd2(u64 a, u64 b) {
  u64 d; asm("add.rn.f32x2 %0, %1, %2;" : "=l"(d) : "l"(a), "l"(b));
  return d;
}
__device__ __forceinline__ u64 fmul2(u64 a, u64 b) {
  u64 d; asm("mul.rn.f32x2 %0, %1, %2;" : "=l"(d) : "l"(a), "l"(b));
  return d;
}

union V4 { float4 f; u64 p[2]; float s[4]; };

struct Smem {
  float A[64 * LDA];        // features (in-place)
  float B[64 * LDA];        // agg / xq / xc scratch
  float WT0[128 * 128];     // weight buffer 0
  float WT1[128 * 128];     // weight buffer 1
  float S[64 * LDS_];       // attention matrix
  u64   masks[64];          // binary adjacency, N=64 phase
  float adjP[16 * LDP];     // pooled float adjacency, N<=16
  float part[512];
  float degw[64], s1[64], s2[64], fit[64];
  float av[64], bv[64], cv[64], vals[64];
  int   perm[64];
  float xsum[640];
  float zz[128], yy[16], lse;
};

// ---------------------------------------------------------------------------
// cp.async weight prefetch: one 64KB matrix, 8 x 16B per thread
// ---------------------------------------------------------------------------
__device__ __forceinline__ void prefetch_wt(float* dst, int widx) {
  unsigned saddr = (unsigned)__cvta_generic_to_shared(dst);
  const char* gsrc = (const char*)(g_WT + widx * 16384);
  int tid = threadIdx.x;
#pragma unroll
  for (int i = 0; i < 8; i++) {
    int o = (tid + i * 512) * 16;
    asm volatile("cp.async.cg.shared.global [%0], [%1], 16;"
                 :: "r"(saddr + o), "l"(gsrc + o));
  }
  asm volatile("cp.async.commit_group;");
}
#define CP_WAIT asm volatile("cp.async.wait_group 0;" ::: "memory")

// ---------------------------------------------------------------------------
// 8x4 GEMM core: acc[r] += L[(i0+r)][k] * W[k][c0..c0+3], k in [0,128)
// ---------------------------------------------------------------------------
__device__ __forceinline__ void mm84(u64 (&acc)[8][2],
    const float* __restrict__ L, const float* __restrict__ W,
    int i0, int c0)
{
  const float* Lp = L + i0 * LDA;
  const float* Wp = W + c0;
#pragma unroll 2
  for (int k = 0; k < 128; k += 4) {
    V4 lv[8];
#pragma unroll
    for (int r = 0; r < 8; r++)
      lv[r].f = *reinterpret_cast<const float4*>(Lp + r * LDA + k);
#pragma unroll
    for (int q = 0; q < 4; q++) {
      V4 rv;
      rv.f = *reinterpret_cast<const float4*>(Wp + (k + q) * 128);
#pragma unroll
      for (int r = 0; r < 8; r++) {
        u64 lp = bcast2(lv[r].s[q]);
        acc[r][0] = ffma2(lp, rv.p[0], acc[r][0]);
        acc[r][1] = ffma2(lp, rv.p[1], acc[r][1]);
      }
    }
  }
}

// ---------------------------------------------------------------------------
// 4x8 GEMM core (kept for small-N convs / pool XQ)
// ---------------------------------------------------------------------------
__device__ __forceinline__ void mm48(u64 (&acc)[4][4],
    const float* __restrict__ L, const float* __restrict__ W,
    int i0, int c0, int k0, int K)
{
  const float* Lp = L + i0 * LDA + k0;
  const float* Wp = W + k0 * 128 + c0;
#pragma unroll 2
  for (int k = 0; k < K; k += 4) {
    V4 lv[4];
#pragma unroll
    for (int r = 0; r < 4; r++)
      lv[r].f = *reinterpret_cast<const float4*>(Lp + r * LDA + k);
#pragma unroll
    for (int q = 0; q < 4; q++) {
      V4 ra, rb;
      ra.f = *reinterpret_cast<const float4*>(Wp + (k + q) * 128);
      rb.f = *reinterpret_cast<const float4*>(Wp + (k + q) * 128 + 64);
#pragma unroll
      for (int r = 0; r < 4; r++) {
        u64 lp = bcast2(lv[r].s[q]);
        acc[r][0] = ffma2(lp, ra.p[0], acc[r][0]);
        acc[r][1] = ffma2(lp, ra.p[1], acc[r][1]);
        acc[r][2] = ffma2(lp, rb.p[0], acc[r][2]);
        acc[r][3] = ffma2(lp, rb.p[1], acc[r][3]);
      }
    }
  }
}

__device__ __forceinline__ void acc_zero(u64 (&acc)[4][4]) {
#pragma unroll
  for (int r = 0; r < 4; r++)
#pragma unroll
    for (int j = 0; j < 4; j++) acc[r][j] = 0ull;
}

__device__ __forceinline__ void tile_store(const u64 (&acc)[4][4],
    float* O, int i0, int c0)
{
#pragma unroll
  for (int r = 0; r < 4; r++) {
    V4 a, b;
    a.p[0] = acc[r][0]; a.p[1] = acc[r][1];
    b.p[0] = acc[r][2]; b.p[1] = acc[r][3];
    *reinterpret_cast<float4*>(O + (i0 + r) * LDA + c0)      = a.f;
    *reinterpret_cast<float4*>(O + (i0 + r) * LDA + c0 + 64) = b.f;
  }
}

// O_tile = acc + P_tile + bias (optional relu)
template<bool RELU>
__device__ __forceinline__ void tile_combine(const u64 (&acc)[4][4],
    const float* __restrict__ P, float* __restrict__ O,
    int i0, int c0, const float* __restrict__ bias)
{
  float4 b1 = *reinterpret_cast<const float4*>(bias + c0);
  float4 b2 = *reinterpret_cast<const float4*>(bias + c0 + 64);
#pragma unroll
  for (int r = 0; r < 4; r++) {
    V4 a, b, o1, o2;
    a.p[0] = acc[r][0]; a.p[1] = acc[r][1];
    b.p[0] = acc[r][2]; b.p[1] = acc[r][3];
    o1.f = *reinterpret_cast<const float4*>(P + (i0 + r) * LDA + c0);
    o2.f = *reinterpret_cast<const float4*>(P + (i0 + r) * LDA + c0 + 64);
    a.f.x += o1.f.x + b1.x; a.f.y += o1.f.y + b1.y;
    a.f.z += o1.f.z + b1.z; a.f.w += o1.f.w + b1.w;
    b.f.x += o2.f.x + b2.x; b.f.y += o2.f.y + b2.y;
    b.f.z += o2.f.z + b2.z; b.f.w += o2.f.w + b2.w;
    if (RELU) {
      a.f.x = fmaxf(a.f.x, 0.f); a.f.y = fmaxf(a.f.y, 0.f);
      a.f.z = fmaxf(a.f.z, 0.f); a.f.w = fmaxf(a.f.w, 0.f);
      b.f.x = fmaxf(b.f.x, 0.f); b.f.y = fmaxf(b.f.y, 0.f);
      b.f.z = fmaxf(b.f.z, 0.f); b.f.w = fmaxf(b.f.w, 0.f);
    }
    *reinterpret_cast<float4*>(O + (i0 + r) * LDA + c0)      = a.f;
    *reinterpret_cast<float4*>(O + (i0 + r) * LDA + c0 + 64) = b.f;
  }
}

__device__ __forceinline__ float warp_red_sum(float v) {
#pragma unroll
  for (int o = 16; o; o >>= 1) v += __shfl_xor_sync(0xffffffffu, v, o);
  return v;
}

// ---------------------------------------------------------------------------
// conv, N=64 (bitmask adjacency): A = relu( (adj@A)/cnt @ Wr + A@Wroot + br )
// Weight GEMMs: 4 groups x 128 threads, 8x4 tiles, column-split.
//   g0: agg@Wr  cols 0-63    g1: agg@Wr  cols 64-127
//   g2: X@Wroot cols 0-63    g3: X@Wroot cols 64-127
// ---------------------------------------------------------------------------
__device__ void conv64(Smem* s, const float* __restrict__ br) {
  const int tid = threadIdx.x;
  // agg = (masks @ A)/cnt -> B  (512 threads, 2 rows x 8 cols, bit iteration)
  {
    const int ti = tid >> 4, th = tid & 15;
    const int i0 = ti * 2, c0 = th * 4;
    u64 m0 = s->masks[i0], m1 = s->masks[i0 + 1];
    u64 a0[4] = {0,0,0,0}, a1[4] = {0,0,0,0};
    u64 mm = m0 | m1;
    const float* Ap = s->A + c0;
    while (mm) {
      int j = __ffsll((long long)mm) - 1;
      mm &= mm - 1;
      V4 ra, rb;
      ra.f = *reinterpret_cast<const float4*>(Ap + j * LDA);
      rb.f = *reinterpret_cast<const float4*>(Ap + j * LDA + 64);
      if ((m0 >> j) & 1) {
        a0[0] = fadd2(a0[0], ra.p[0]); a0[1] = fadd2(a0[1], ra.p[1]);
        a0[2] = fadd2(a0[2], rb.p[0]); a0[3] = fadd2(a0[3], rb.p[1]);
      }
      if ((m1 >> j) & 1) {
        a1[0] = fadd2(a1[0], ra.p[0]); a1[1] = fadd2(a1[1], ra.p[1]);
        a1[2] = fadd2(a1[2], rb.p[0]); a1[3] = fadd2(a1[3], rb.p[1]);
      }
    }
    u64 r0 = bcast2(1.f / fmaxf((float)__popcll(m0), 1.f));
    u64 r1 = bcast2(1.f / fmaxf((float)__popcll(m1), 1.f));
    V4 o;
    o.p[0] = fmul2(a0[0], r0); o.p[1] = fmul2(a0[1], r0);
    *reinterpret_cast<float4*>(s->B + i0 * LDA + c0) = o.f;
    o.p[0] = fmul2(a0[2], r0); o.p[1] = fmul2(a0[3], r0);
    *reinterpret_cast<float4*>(s->B + i0 * LDA + c0 + 64) = o.f;
    o.p[0] = fmul2(a1[0], r1); o.p[1] = fmul2(a1[1], r1);
    *reinterpret_cast<float4*>(s->B + (i0 + 1) * LDA + c0) = o.f;
    o.p[0] = fmul2(a1[2], r1); o.p[1] = fmul2(a1[3], r1);
    *reinterpret_cast<float4*>(s->B + (i0 + 1) * LDA + c0 + 64) = o.f;
  }
  CP_WAIT;
  __syncthreads();

  // 4-group 8x4 GEMMs
  const int grp = tid >> 7;          // 0..3
  const int t   = tid & 127;
  const int i0  = (t >> 4) * 8;      // 8 row-groups of 8
  const int c0  = (grp & 1) * 64 + (t & 15) * 4;
  u64 acc[8][2];
#pragma unroll
  for (int r = 0; r < 8; r++) { acc[r][0] = 0ull; acc[r][1] = 0ull; }
  if (grp < 2) mm84(acc, s->B, s->WT0, i0, c0);   // agg @ Wr
  else         mm84(acc, s->A, s->WT1, i0, c0);   // X @ Wroot
  __syncthreads();
  if (grp >= 2) {   // store Wroot partial into B (agg is dead)
#pragma unroll
    for (int r = 0; r < 8; r++) {
      V4 a; a.p[0] = acc[r][0]; a.p[1] = acc[r][1];
      *reinterpret_cast<float4*>(s->B + (i0 + r) * LDA + c0) = a.f;
    }
  }
  __syncthreads();
  if (grp < 2) {    // combine + bias + relu -> A (in place)
    float4 bb = *reinterpret_cast<const float4*>(br + c0);
#pragma unroll
    for (int r = 0; r < 8; r++) {
      V4 a, o;
      a.p[0] = acc[r][0]; a.p[1] = acc[r][1];
      o.f = *reinterpret_cast<const float4*>(s->B + (i0 + r) * LDA + c0);
      a.f.x = fmaxf(a.f.x + o.f.x + bb.x, 0.f);
      a.f.y = fmaxf(a.f.y + o.f.y + bb.y, 0.f);
      a.f.z = fmaxf(a.f.z + o.f.z + bb.z, 0.f);
      a.f.w = fmaxf(a.f.w + o.f.w + bb.w, 0.f);
      *reinterpret_cast<float4*>(s->A + (i0 + r) * LDA + c0) = a.f;
    }
  }
  __syncthreads();
}

// ---------------------------------------------------------------------------
// conv, N<=16 (float adjP)
// ---------------------------------------------------------------------------
template<int NI>
__device__ void conv_small(Smem* s, const float* __restrict__ br) {
  const int tid = threadIdx.x;
  if (tid < NI * 16) {
    int row = tid >> 4, c0 = (tid & 15) * 4;
    float a[8] = {0,0,0,0,0,0,0,0};
    int cnt = 0;
    for (int j = 0; j < NI; j++) {
      float v = s->adjP[row * LDP + j];
      if (v != 0.f) {
        cnt++;
        V4 ra, rb;
        ra.f = *reinterpret_cast<const float4*>(s->A + j * LDA + c0);
        rb.f = *reinterpret_cast<const float4*>(s->A + j * LDA + c0 + 64);
        a[0] = fmaf(v, ra.s[0], a[0]); a[1] = fmaf(v, ra.s[1], a[1]);
        a[2] = fmaf(v, ra.s[2], a[2]); a[3] = fmaf(v, ra.s[3], a[3]);
        a[4] = fmaf(v, rb.s[0], a[4]); a[5] = fmaf(v, rb.s[1], a[5]);
        a[6] = fmaf(v, rb.s[2], a[6]); a[7] = fmaf(v, rb.s[3], a[7]);
      }
    }
    float rc = 1.f / fmaxf((float)cnt, 1.f);
    *reinterpret_cast<float4*>(s->B + row * LDA + c0) =
        make_float4(a[0]*rc, a[1]*rc, a[2]*rc, a[3]*rc);
    *reinterpret_cast<float4*>(s->B + row * LDA + c0 + 64) =
        make_float4(a[4]*rc, a[5]*rc, a[6]*rc, a[7]*rc);
  }
  CP_WAIT;
  __syncthreads();

  const int g = tid >> 8, t = tid & 255;
  const int i0 = (t >> 4) * 4, c0 = (t & 15) * 4;
  const bool act = i0 < NI;
  u64 acc[4][4];
  acc_zero(acc);
  if (act) {
    if (g == 0) mm48(acc, s->B, s->WT0, i0, c0, 0, 128);
    else        mm48(acc, s->A, s->WT1, i0, c0, 0, 128);
  }
  __syncthreads();
  if (g == 1 && act) tile_store(acc, s->B, i0, c0);
  __syncthreads();
  if (g == 0 && act) tile_combine<true>(acc, s->B, s->A, i0, c0, br);
  __syncthreads();
}

// ---------------------------------------------------------------------------
// mean pool of A rows -> xsum[stage]
// ---------------------------------------------------------------------------
__device__ void mean_pool(Smem* s, int NI, int stage) {
  const int tid = threadIdx.x;
  int q = tid >> 7, h = tid & 127;
  float a = 0.f;
  for (int r = q; r < NI; r += 4) a += s->A[r * LDA + h];
  s->part[q * 128 + h] = a;
  __syncthreads();
  if (tid < 128)
    s->xsum[stage * 128 + tid] =
        (s->part[tid] + s->part[128 + tid] + s->part[256 + tid] + s->part[384 + tid])
        * (1.f / (float)NI);
  __syncthreads();
}

// ---------------------------------------------------------------------------
// top-k (warp 0) — matches jax top_k (lowest index on ties)
// ---------------------------------------------------------------------------
template<int KK>
__device__ void topk(Smem* s, int NI) {
  if (threadIdx.x < 32) {
    int lane = threadIdx.x;
    float v0 = (lane < NI) ? s->fit[lane] : -2.f;
    float v1 = (lane + 32 < NI) ? s->fit[lane + 32] : -2.f;
#pragma unroll 1
    for (int t = 0; t < KK; t++) {
      float bv; int bi;
      if (v0 >= v1) { bv = v0; bi = lane; } else { bv = v1; bi = lane + 32; }
#pragma unroll
      for (int o = 16; o; o >>= 1) {
        float ov = __shfl_xor_sync(0xffffffffu, bv, o);
        int   oi = __shfl_xor_sync(0xffffffffu, bi, o);
        if (ov > bv || (ov == bv && oi < bi)) { bv = ov; bi = oi; }
      }
      if (lane == 0) { s->perm[t] = bi; s->vals[t] = bv; }
      if (bi == lane) v0 = -2.f;
      if (bi == lane + 32) v1 = -2.f;
    }
  }
}

// ---------------------------------------------------------------------------
// ASAP pool 1 (N=64 -> 16, bitmask adjacency; lw^T expected in WT0)
// ---------------------------------------------------------------------------
__device__ void pool1(Smem* s,
    const float* __restrict__ lb, const float* __restrict__ aw, float ab,
    const float* __restrict__ l1w, float l1b,
    const float* __restrict__ l2w,
    const float* __restrict__ l3w, float l3b)
{
  const int tid = threadIdx.x;
  const int w = tid >> 5, lane = tid & 31;

  if (tid < 64) s->masks[tid] |= (1ull << tid);   // adj1 diagonal
  __syncthreads();
  if (tid < 64) s->degw[tid] = (float)__popcll(s->masks[tid]);

  // masked max-agg -> B (2 rows x 8 cols per thread)
  {
    const int ti = tid >> 4, th = tid & 15;
    const int i0 = ti * 2, c0 = th * 4;
    u64 m0 = s->masks[i0], m1 = s->masks[i0 + 1];
    float a0[8], a1[8];
#pragma unroll
    for (int c = 0; c < 8; c++) { a0[c] = -1e30f; a1[c] = -1e30f; }
    u64 mm = m0 | m1;
    const float* Ap = s->A + c0;
    while (mm) {
      int j = __ffsll((long long)mm) - 1;
      mm &= mm - 1;
      V4 ra, rb;
      ra.f = *reinterpret_cast<const float4*>(Ap + j * LDA);
      rb.f = *reinterpret_cast<const float4*>(Ap + j * LDA + 64);
      if ((m0 >> j) & 1) {
        a0[0]=fmaxf(a0[0],ra.s[0]); a0[1]=fmaxf(a0[1],ra.s[1]);
        a0[2]=fmaxf(a0[2],ra.s[2]); a0[3]=fmaxf(a0[3],ra.s[3]);
        a0[4]=fmaxf(a0[4],rb.s[0]); a0[5]=fmaxf(a0[5],rb.s[1]);
        a0[6]=fmaxf(a0[6],rb.s[2]); a0[7]=fmaxf(a0[7],rb.s[3]);
      }
      if ((m1 >> j) & 1) {
        a1[0]=fmaxf(a1[0],ra.s[0]); a1[1]=fmaxf(a1[1],ra.s[1]);
        a1[2]=fmaxf(a1[2],ra.s[2]); a1[3]=fmaxf(a1[3],ra.s[3]);
        a1[4]=fmaxf(a1[4],rb.s[0]); a1[5]=fmaxf(a1[5],rb.s[1]);
        a1[6]=fmaxf(a1[6],rb.s[2]); a1[7]=fmaxf(a1[7],rb.s[3]);
      }
    }
    *reinterpret_cast<float4*>(s->B + i0*LDA + c0) = make_float4(a0[0],a0[1],a0[2],a0[3]);
    *reinterpret_cast<float4*>(s->B + i0*LDA + c0 + 64) = make_float4(a0[4],a0[5],a0[6],a0[7]);
    *reinterpret_cast<float4*>(s->B + (i0+1)*LDA + c0) = make_float4(a1[0],a1[1],a1[2],a1[3]);
    *reinterpret_cast<float4*>(s->B + (i0+1)*LDA + c0 + 64) = make_float4(a1[4],a1[5],a1[6],a1[7]);
  }
  CP_WAIT;
  __syncthreads();

  // XQ = B @ lw^T + lb -> B  (K-split dual group)
  {
    const int g = tid >> 8, t = tid & 255;
    const int i0 = (t >> 4) * 4, c0 = (t & 15) * 4;
    u64 acc[4][4];
    acc_zero(acc);
    mm48(acc, s->B, s->WT0, i0, c0, g ? 64 : 0, 64);
    __syncthreads();
    if (g == 1) tile_store(acc, s->B, i0, c0);
    __syncthreads();
    if (g == 0) tile_combine<false>(acc, s->B, s->B, i0, c0, lb);
  }
  __syncthreads();

  // s1 = XQ.aw[:128] (B), s2 = X.aw[128:] (A)
  for (int d = w; d < 128; d += 16) {
    const float* row = (d < 64) ? (s->B + d * LDA) : (s->A + (d - 64) * LDA);
    const float* wv = (d < 64) ? aw : (aw + 128);
    float4 a = reinterpret_cast<const float4*>(row)[lane];
    float4 b = reinterpret_cast<const float4*>(wv)[lane];
    float dot = warp_red_sum(a.x*b.x + a.y*b.y + a.z*b.z + a.w*b.w);
    if (lane == 0) { if (d < 64) s->s1[d] = dot; else s->s2[d - 64] = dot; }
  }
  __syncthreads();

  // masked softmax attention -> S (full 64 cols written; 0 where unmasked)
  for (int i = w; i < 64; i += 16) {
    u64 mi = s->masks[i];
    float s1i = s->s1[i];
    bool vA = (mi >> lane) & 1, vB = (mi >> (lane + 32)) & 1;
    float e0 = s1i + s->s2[lane] + ab;       e0 = (e0 > 0.f) ? e0 : SLOPE * e0;
    float e1 = s1i + s->s2[lane + 32] + ab;  e1 = (e1 > 0.f) ? e1 : SLOPE * e1;
    float ev0 = vA ? e0 : -1e30f, ev1 = vB ? e1 : -1e30f;
    float mx = fmaxf(ev0, ev1);
#pragma unroll
    for (int o = 16; o; o >>= 1) mx = fmaxf(mx, __shfl_xor_sync(0xffffffffu, mx, o));
    float ex0 = vA ? __expf(ev0 - mx) : 0.f;
    float ex1 = vB ? __expf(ev1 - mx) : 0.f;
    float sum = warp_red_sum(ex0 + ex1);
    float inv = 1.f / sum;
    s->S[i * LDS_ + lane]      = ex0 * inv;
    s->S[i * LDS_ + lane + 32] = ex1 * inv;
  }
  __syncthreads();

  // XC = S @ X -> B  (2x8 tiles, zero-skip)
  {
    const int ti = tid >> 4, th = tid & 15;
    const int i0 = ti * 2, c0 = th * 4;
    u64 a0[4] = {0,0,0,0}, a1[4] = {0,0,0,0};
    for (int k = 0; k < 64; k++) {
      float l0 = s->S[i0 * LDS_ + k], l1 = s->S[(i0 + 1) * LDS_ + k];
      if (l0 == 0.f && l1 == 0.f) continue;
      V4 ra, rb;
      ra.f = *reinterpret_cast<const float4*>(s->A + k * LDA + c0);
      rb.f = *reinterpret_cast<const float4*>(s->A + k * LDA + c0 + 64);
      if (l0 != 0.f) {
        u64 lp = bcast2(l0);
        a0[0]=ffma2(lp,ra.p[0],a0[0]); a0[1]=ffma2(lp,ra.p[1],a0[1]);
        a0[2]=ffma2(lp,rb.p[0],a0[2]); a0[3]=ffma2(lp,rb.p[1],a0[3]);
      }
      if (l1 != 0.f) {
        u64 lp = bcast2(l1);
        a1[0]=ffma2(lp,ra.p[0],a1[0]); a1[1]=ffma2(lp,ra.p[1],a1[1]);
        a1[2]=ffma2(lp,rb.p[0],a1[2]); a1[3]=ffma2(lp,rb.p[1],a1[3]);
      }
    }
    V4 o;
    o.p[0]=a0[0]; o.p[1]=a0[1]; *reinterpret_cast<float4*>(s->B + i0*LDA + c0) = o.f;
    o.p[0]=a0[2]; o.p[1]=a0[3]; *reinterpret_cast<float4*>(s->B + i0*LDA + c0 + 64) = o.f;
    o.p[0]=a1[0]; o.p[1]=a1[1]; *reinterpret_cast<float4*>(s->B + (i0+1)*LDA + c0) = o.f;
    o.p[0]=a1[2]; o.p[1]=a1[3]; *reinterpret_cast<float4*>(s->B + (i0+1)*LDA + c0 + 64) = o.f;
  }
  __syncthreads();

  // av/bv/cv dots
  for (int d = w; d < 192; d += 16) {
    int grp = d >> 6, i = d & 63;
    const float* wv = (grp == 0) ? l1w : (grp == 1) ? l2w : l3w;
    float4 a = reinterpret_cast<const float4*>(s->B + i * LDA)[lane];
    float4 b = reinterpret_cast<const float4*>(wv)[lane];
    float dot = warp_red_sum(a.x*b.x + a.y*b.y + a.z*b.z + a.w*b.w);
    if (lane == 0) {
      if (grp == 0)      s->av[i] = dot + l1b;
      else if (grp == 1) s->bv[i] = dot;
      else               s->cv[i] = dot + l3b;
    }
  }
  __syncthreads();

  // fit = sigmoid( adj1@av - bv*degw + cv )
  if (tid < 64) {
    u64 mm = s->masks[tid];
    float a = 0.f;
    while (mm) {
      int j = __ffsll((long long)mm) - 1;
      mm &= mm - 1;
      a += s->av[j];
    }
    float f = a - s->bv[tid] * s->degw[tid] + s->cv[tid];
    s->fit[tid] = 1.f / (1.f + expf(-f));
  }
  __syncthreads();
  topk<16>(s, 64);
  __syncthreads();

  // XN = XC[perm]*vals -> A rows 0..15 ; T = S[perm]@adj1 -> A rows 16..31
  for (int idx = tid; idx < 16 * 128; idx += THREADS) {
    int t2 = idx >> 7, h = idx & 127;
    s->A[t2 * LDA + h] = s->B[s->perm[t2] * LDA + h] * s->vals[t2];
  }
  for (int idx = tid; idx < 16 * 64; idx += THREADS) {
    int t2 = idx >> 6, m = idx & 63;
    const float* srow = s->S + s->perm[t2] * LDS_;
    float a = 0.f;
    for (int n = 0; n < 64; n++) {
      float sv = srow[n];
      if (sv != 0.f && ((s->masks[n] >> m) & 1)) a += sv;
    }
    s->A[(16 + t2) * LDA + m] = a;
  }
  __syncthreads();

  // adjn = T @ S[perm]^T, zero diag -> adjP
  if (tid < 256) {
    int t2 = tid >> 4, l = tid & 15;
    const float* sl = s->S + s->perm[l] * LDS_;
    const float* tr = s->A + (16 + t2) * LDA;
    float a = 0.f;
    for (int m = 0; m < 64; m++) a += tr[m] * sl[m];
    s->adjP[t2 * LDP + l] = (t2 == l) ? 0.f : a;
  }
  __syncthreads();
}

// ---------------------------------------------------------------------------
// ASAP pool 2 (N=16 -> 4, float adjP; lw^T expected in WT0)
// ---------------------------------------------------------------------------
__device__ void pool2(Smem* s,
    const float* __restrict__ lb, const float* __restrict__ aw, float ab,
    const float* __restrict__ l1w, float l1b,
    const float* __restrict__ l2w,
    const float* __restrict__ l3w, float l3b)
{
  const int tid = threadIdx.x;
  const int w = tid >> 5, lane = tid & 31;

  if (tid < 16) {
    float d = s->adjP[tid * LDP + tid];
    if (d == 0.f) s->adjP[tid * LDP + tid] = 1.f;
  }
  __syncthreads();
  if (tid < 16) {
    float sum = 0.f;
    for (int j = 0; j < 16; j++) sum += s->adjP[tid * LDP + j];
    s->degw[tid] = sum;
  }

  // masked max-agg -> B
  if (tid < 256) {
    int row = tid >> 4, c0 = (tid & 15) * 4;
    float a[8];
#pragma unroll
    for (int c = 0; c < 8; c++) a[c] = -1e30f;
    for (int j = 0; j < 16; j++) {
      if (s->adjP[row * LDP + j] != 0.f) {
        V4 ra, rb;
        ra.f = *reinterpret_cast<const float4*>(s->A + j * LDA + c0);
        rb.f = *reinterpret_cast<const float4*>(s->A + j * LDA + c0 + 64);
        a[0]=fmaxf(a[0],ra.s[0]); a[1]=fmaxf(a[1],ra.s[1]);
        a[2]=fmaxf(a[2],ra.s[2]); a[3]=fmaxf(a[3],ra.s[3]);
        a[4]=fmaxf(a[4],rb.s[0]); a[5]=fmaxf(a[5],rb.s[1]);
        a[6]=fmaxf(a[6],rb.s[2]); a[7]=fmaxf(a[7],rb.s[3]);
      }
    }
    *reinterpret_cast<float4*>(s->B + row*LDA + c0) = make_float4(a[0],a[1],a[2],a[3]);
    *reinterpret_cast<float4*>(s->B + row*LDA + c0 + 64) = make_float4(a[4],a[5],a[6],a[7]);
  }
  CP_WAIT;
  __syncthreads();

  // XQ = B @ lw^T + lb -> B  (K-split dual group, 16 rows)
  {
    const int g = tid >> 8, t = tid & 255;
    const int i0 = (t >> 4) * 4, c0 = (t & 15) * 4;
    const bool act = i0 < 16;
    u64 acc[4][4];
    acc_zero(acc);
    if (act) mm48(acc, s->B, s->WT0, i0, c0, g ? 64 : 0, 64);
    __syncthreads();
    if (g == 1 && act) tile_store(acc, s->B, i0, c0);
    __syncthreads();
    if (g == 0 && act) tile_combine<false>(acc, s->B, s->B, i0, c0, lb);
  }
  __syncthreads();

  // s1/s2
  for (int d = w; d < 32; d += 16) {
    const float* row = (d < 16) ? (s->B + d * LDA) : (s->A + (d - 16) * LDA);
    const float* wv = (d < 16) ? aw : (aw + 128);
    float4 a = reinterpret_cast<const float4*>(row)[lane];
    float4 b = reinterpret_cast<const float4*>(wv)[lane];
    float dot = warp_red_sum(a.x*b.x + a.y*b.y + a.z*b.z + a.w*b.w);
    if (lane == 0) { if (d < 16) s->s1[d] = dot; else s->s2[d - 16] = dot; }
  }
  __syncthreads();

  // attention (one warp per row, 16 rows)
  if (w < 16) {
    int i = w;
    float adjv = (lane < 16) ? s->adjP[i * LDP + lane] : 0.f;
    float e = s->s1[i] + ((lane < 16) ? s->s2[lane] : 0.f) + ab;
    e = (e > 0.f) ? e : SLOPE * e;
    float ev = (adjv != 0.f) ? e : -1e30f;
    float mx = ev;
#pragma unroll
    for (int o = 16; o; o >>= 1) mx = fmaxf(mx, __shfl_xor_sync(0xffffffffu, mx, o));
    float ex = (adjv != 0.f) ? __expf(ev - mx) : 0.f;
    float sum = warp_red_sum(ex);
    if (lane < 16) s->S[i * LDS_ + lane] = ex / sum;
  }
  __syncthreads();

  // XC = S @ X -> B
  if (tid < 256) {
    int row = tid >> 4, c0 = (tid & 15) * 4;
    float a[8] = {0,0,0,0,0,0,0,0};
    for (int j = 0; j < 16; j++) {
      float sv = s->S[row * LDS_ + j];
      if (sv != 0.f) {
        V4 ra, rb;
        ra.f = *reinterpret_cast<const float4*>(s->A + j * LDA + c0);
        rb.f = *reinterpret_cast<const float4*>(s->A + j * LDA + c0 + 64);
        a[0]=fmaf(sv,ra.s[0],a[0]); a[1]=fmaf(sv,ra.s[1],a[1]);
        a[2]=fmaf(sv,ra.s[2],a[2]); a[3]=fmaf(sv,ra.s[3],a[3]);
        a[4]=fmaf(sv,rb.s[0],a[4]); a[5]=fmaf(sv,rb.s[1],a[5]);
        a[6]=fmaf(sv,rb.s[2],a[6]); a[7]=fmaf(sv,rb.s[3],a[7]);
      }
    }
    *reinterpret_cast<float4*>(s->B + row*LDA + c0) = make_float4(a[0],a[1],a[2],a[3]);
    *reinterpret_cast<float4*>(s->B + row*LDA + c0 + 64) = make_float4(a[4],a[5],a[6],a[7]);
  }
  __syncthreads();

  // av/bv/cv
  for (int d = w; d < 48; d += 16) {
    int grp = d >> 4, i = d & 15;
    const float* wv = (grp == 0) ? l1w : (grp == 1) ? l2w : l3w;
    float4 a = reinterpret_cast<const float4*>(s->B + i * LDA)[lane];
    float4 b = reinterpret_cast<const float4*>(wv)[lane];
    float dot = warp_red_sum(a.x*b.x + a.y*b.y + a.z*b.z + a.w*b.w);
    if (lane == 0) {
      if (grp == 0)      s->av[i] = dot + l1b;
      else if (grp == 1) s->bv[i] = dot;
      else               s->cv[i] = dot + l3b;
    }
  }
  __syncthreads();

  if (tid < 16) {
    float a = 0.f;
    for (int j = 0; j < 16; j++) a += s->adjP[tid * LDP + j] * s->av[j];
    float f = a - s->bv[tid] * s->degw[tid] + s->cv[tid];
    s->fit[tid] = 1.f / (1.f + expf(-f));
  }
  __syncthreads();
  topk<4>(s, 16);
  __syncthreads();

  // XN -> A rows 0..3 ; T -> A rows 16..19
  {
    int t2 = tid >> 7, h = tid & 127;
    s->A[t2 * LDA + h] = s->B[s->perm[t2] * LDA + h] * s->vals[t2];
  }
  if (tid < 64) {
    int t2 = tid >> 4, m = tid & 15;
    const float* srow = s->S + s->perm[t2] * LDS_;
    float a = 0.f;
    for (int n = 0; n < 16; n++) a += srow[n] * s->adjP[n * LDP + m];
    s->A[(16 + t2) * LDA + m] = a;
  }
  __syncthreads();
  if (tid < 16) {
    int t2 = tid >> 2, l = tid & 3;
    const float* sl = s->S + s->perm[l] * LDS_;
    const float* tr = s->A + (16 + t2) * LDA;
    float a = 0.f;
    for (int m = 0; m < 16; m++) a += tr[m] * sl[m];
    s->adjP[t2 * LDP + l] = (t2 == l) ? 0.f : a;
  }
  __syncthreads();
}

// ---------------------------------------------------------------------------
// main kernel
// ---------------------------------------------------------------------------
__global__ void __launch_bounds__(THREADS, 1) asap_kernel(
    const float* __restrict__ x,          const float* __restrict__ adj,
    const float* __restrict__ conv1_br,
    const float* __restrict__ convs_br,
    const float* __restrict__ pool_lin_b,
    const float* __restrict__ pool_att_w, const float* __restrict__ pool_att_b,
    const float* __restrict__ pool_le1_w, const float* __restrict__ pool_le1_b,
    const float* __restrict__ pool_le2_w,
    const float* __restrict__ pool_le3_w, const float* __restrict__ pool_le3_b,
    const float* __restrict__ lin1_w,     const float* __restrict__ lin1_b,
    const float* __restrict__ lin2_w,     const float* __restrict__ lin2_b,
    float* __restrict__ out)
{
  extern __shared__ unsigned char smraw[];
  Smem* s = reinterpret_cast<Smem*>(smraw);
  const int g = blockIdx.x, tid = threadIdx.x;
  const int w = tid >> 5, lane = tid & 31;

  prefetch_wt(s->WT0, 0);
  prefetch_wt(s->WT1, 1);

  // load features (float4, re-strided to LDA) + binary adjacency -> masks
  {
    const float4* xs = reinterpret_cast<const float4*>(x + (size_t)g * 8192);
#pragma unroll
    for (int i = 0; i < 4; i++) {
      int idx = tid + i * 512;
      int row = idx >> 5, c = (idx & 31) * 4;
      *reinterpret_cast<float4*>(s->A + row * LDA + c) = xs[idx];
    }
    if (tid < 64) {
      const float4* ar = reinterpret_cast<const float4*>(adj + (size_t)g * 4096 + tid * 64);
      u64 m = 0;
#pragma unroll
      for (int c = 0; c < 16; c++) {
        float4 v = __ldg(ar + c);
        if (v.x != 0.f) m |= 1ull << (c * 4 + 0);
        if (v.y != 0.f) m |= 1ull << (c * 4 + 1);
        if (v.z != 0.f) m |= 1ull << (c * 4 + 2);
        if (v.w != 0.f) m |= 1ull << (c * 4 + 3);
      }
      s->masks[tid] = m;
    }
  }
  __syncthreads();

  conv64(s, conv1_br);                 // WT 0,1
  prefetch_wt(s->WT0, 2);
  prefetch_wt(s->WT1, 6);
  mean_pool(s, 64, 0);

  conv64(s, convs_br);                 // WT 2,6
  prefetch_wt(s->WT0, 10);
  mean_pool(s, 64, 1);

  pool1(s, pool_lin_b, pool_att_w, pool_att_b[0],
        pool_le1_w, pool_le1_b[0], pool_le2_w, pool_le3_w, pool_le3_b[0]);
  prefetch_wt(s->WT0, 3);
  prefetch_wt(s->WT1, 7);

  conv_small<16>(s, convs_br + 128);   // WT 3,7
  prefetch_wt(s->WT0, 4);
  prefetch_wt(s->WT1, 8);
  mean_pool(s, 16, 2);

  conv_small<16>(s, convs_br + 256);   // WT 4,8
  prefetch_wt(s->WT0, 11);
  mean_pool(s, 16, 3);

  pool2(s, pool_lin_b + 128, pool_att_w + 256, pool_att_b[1],
        pool_le1_w + 128, pool_le1_b[1], pool_le2_w + 128,
        pool_le3_w + 128, pool_le3_b[1]);
  prefetch_wt(s->WT0, 5);
  prefetch_wt(s->WT1, 9);

  conv_small<4>(s, convs_br + 384);    // WT 5,9
  mean_pool(s, 4, 4);

  // MLP head
  for (int d = w; d < 128; d += 16) {
    const float4* zr = reinterpret_cast<const float4*>(s->xsum);
    const float4* wr = reinterpret_cast<const float4*>(lin1_w + d * 640);
    float a = 0.f;
#pragma unroll
    for (int c = 0; c < 5; c++) {
      float4 zc = zr[lane + 32 * c];
      float4 wc = wr[lane + 32 * c];
      a += zc.x*wc.x + zc.y*wc.y + zc.z*wc.z + zc.w*wc.w;
    }
    a = warp_red_sum(a);
    if (lane == 0) s->zz[d] = fmaxf(a + lin1_b[d], 0.f);
  }
  __syncthreads();
  for (int d = w; d < 10; d += 16) {
    float4 zc = reinterpret_cast<const float4*>(s->zz)[lane];
    float4 wc = reinterpret_cast<const float4*>(lin2_w + d * 128)[lane];
    float a = warp_red_sum(zc.x*wc.x + zc.y*wc.y + zc.z*wc.z + zc.w*wc.w);
    if (lane == 0) s->yy[d] = a + lin2_b[d];
  }
  __syncthreads();
  if (tid == 0) {
    float mx = -1e30f;
    for (int c = 0; c < 10; c++) mx = fmaxf(mx, s->yy[c]);
    float sum = 0.f;
    for (int c = 0; c < 10; c++) sum += expf(s->yy[c] - mx);
    s->lse = mx + logf(sum);
  }
  __syncthreads();
  if (tid < 10) out[g * 10 + tid] = s->yy[tid] - s->lse;
}

// ---------------------------------------------------------------------------
// prologue: transpose the 12 [128x128] weight matrices into g_WT
// ---------------------------------------------------------------------------
__global__ void transpose_k(
    const float* __restrict__ conv1_wr, const float* __restrict__ conv1_wroot,
    const float* __restrict__ convs_wr, const float* __restrict__ convs_wroot,
    const float* __restrict__ pool_lin_w)
{
  __shared__ float t[32][33];
  int mat = blockIdx.y;
  int tile = blockIdx.x;
  int tx = tile & 3, ty = tile >> 2;
  const float* src =
      (mat == 0) ? conv1_wr :
      (mat == 1) ? conv1_wroot :
      (mat < 6)  ? convs_wr + (mat - 2) * 16384 :
      (mat < 10) ? convs_wroot + (mat - 6) * 16384 :
                   pool_lin_w + (mat - 10) * 16384;
#pragma unroll
  for (int r = threadIdx.y; r < 32; r += 8)
    t[r][threadIdx.x] = src[(ty * 32 + r) * 128 + tx * 32 + threadIdx.x];
  __syncthreads();
#pragma unroll
  for (int r = threadIdx.y; r < 32; r += 8)
    g_WT[mat * 16384 + (tx * 32 + r) * 128 + ty * 32 + threadIdx.x] = t[threadIdx.x][r];
}

// ---------------------------------------------------------------------------
// launch
// ---------------------------------------------------------------------------
extern "C" void kernel_launch(void* const* d_in, const int* in_sizes, int n_in,
                              void* d_out, int out_size)
{
  const float* x           = (const float*)d_in[0];
  const float* adj         = (const float*)d_in[1];
  const float* conv1_wr    = (const float*)d_in[2];
  const float* conv1_br    = (const float*)d_in[3];
  const float* conv1_wroot = (const float*)d_in[4];
  const float* convs_wr    = (const float*)d_in[5];
  const float* convs_br    = (const float*)d_in[6];
  const float* convs_wroot = (const float*)d_in[7];
  const float* pool_lin_w  = (const float*)d_in[8];
  const float* pool_lin_b  = (const float*)d_in[9];
  const float* pool_att_w  = (const float*)d_in[10];
  const float* pool_att_b  = (const float*)d_in[11];
  const float* pool_le1_w  = (const float*)d_in[12];
  const float* pool_le1_b  = (const float*)d_in[13];
  const float* pool_le2_w  = (const float*)d_in[14];
  const float* pool_le3_w  = (const float*)d_in[15];
  const float* pool_le3_b  = (const float*)d_in[16];
  const float* lin1_w      = (const float*)d_in[17];
  const float* lin1_b      = (const float*)d_in[18];
  const float* lin2_w      = (const float*)d_in[19];
  const float* lin2_b      = (const float*)d_in[20];
  float* out = (float*)d_out;

  transpose_k<<<dim3(16, 12), dim3(32, 8)>>>(
      conv1_wr, conv1_wroot, convs_wr, convs_wroot, pool_lin_w);

  cudaFuncSetAttribute(asap_kernel, cudaFuncAttributeMaxDynamicSharedMemorySize,
                       (int)sizeof(Smem));
  asap_kernel<<<G_TOT, THREADS, sizeof(Smem)>>>(
      x, adj, conv1_br, convs_br,
      pool_lin_b, pool_att_w, pool_att_b,
      pool_le1_w, pool_le1_b, pool_le2_w, pool_le3_w, pool_le3_b,
      lin1_w, lin1_b, lin2_w, lin2_b, out);
}

// round 7
// speedup vs baseline: 1.3037x; 1.0330x over previous
#include <cuda_runtime.h>
#include <math.h>

// Net_ASAP fused pipeline, round 7 (= round 6 + pool2 XN write fix).
// - 256 threads/CTA, 2 CTAs/SM (smem ~93KB, regs<=128 via launch_bounds).
// - Weight GEMMs read pre-transposed weights straight from global (L1/L2
//   resident, shared across all CTAs) -> no smem weight buffers.
// - 8x8 register tiles for the big GEMMs; bitmask adjacency; in-place A.

#define THREADS 256
#define G_TOT 512
#define SLOPE 0.2f
#define LDA 132
#define LDS_ 68
#define LDP 17

typedef unsigned long long u64;

__device__ float g_WT[12 * 128 * 128];   // pre-transposed weights W^T[k][h]

__device__ __forceinline__ u64 bcast2(float v) {
  unsigned r = __float_as_uint(v);
  u64 d; asm("mov.b64 %0, {%1, %1};" : "=l"(d) : "r"(r));
  return d;
}
__device__ __forceinline__ u64 ffma2(u64 a, u64 b, u64 c) {
  u64 d; asm("fma.rn.f32x2 %0, %1, %2, %3;" : "=l"(d) : "l"(a), "l"(b), "l"(c));
  return d;
}
__device__ __forceinline__ u64 fadd2(u64 a, u64 b) {
  u64 d; asm("add.rn.f32x2 %0, %1, %2;" : "=l"(d) : "l"(a), "l"(b));
  return d;
}
__device__ __forceinline__ u64 fmul2(u64 a, u64 b) {
  u64 d; asm("mul.rn.f32x2 %0, %1, %2;" : "=l"(d) : "l"(a), "l"(b));
  return d;
}

union V4 { float4 f; u64 p[2]; float s[4]; };

struct Smem {
  float A[64 * LDA];        // features (in-place)
  float B[64 * LDA];        // agg / xq / xc scratch
  float S[64 * LDS_];       // attention matrix
  u64   masks[64];          // binary adjacency, N=64 phase
  float adjP[16 * LDP];     // pooled float adjacency, N<=16
  float part[256];
  float degw[64], s1[64], s2[64], fit[64];
  float av[64], bv[64], cv[64], vals[64];
  int   perm[64];
  float xsum[640];
  float zz[128], yy[16], lse;
};

// ---------------------------------------------------------------------------
// 8x8 GEMM core: acc[r][0..3] += L[(i0+r)][k] * W[k][c0..c0+7], W in GLOBAL
// ---------------------------------------------------------------------------
__device__ __forceinline__ void mm88(u64 (&acc)[8][4],
    const float* __restrict__ L, const float* __restrict__ W,
    int i0, int c0, int k0, int K)
{
  const float* Lp = L + i0 * LDA + k0;
  const float* Wp = W + k0 * 128 + c0;
#pragma unroll 1
  for (int k = 0; k < K; k += 4) {
    V4 wv[4][2];
#pragma unroll
    for (int q = 0; q < 4; q++) {
      wv[q][0].f = __ldg(reinterpret_cast<const float4*>(Wp + (k + q) * 128));
      wv[q][1].f = __ldg(reinterpret_cast<const float4*>(Wp + (k + q) * 128 + 4));
    }
#pragma unroll
    for (int r = 0; r < 8; r++) {
      V4 lv; lv.f = *reinterpret_cast<const float4*>(Lp + r * LDA + k);
#pragma unroll
      for (int q = 0; q < 4; q++) {
        u64 lp = bcast2(lv.s[q]);
        acc[r][0] = ffma2(lp, wv[q][0].p[0], acc[r][0]);
        acc[r][1] = ffma2(lp, wv[q][0].p[1], acc[r][1]);
        acc[r][2] = ffma2(lp, wv[q][1].p[0], acc[r][2]);
        acc[r][3] = ffma2(lp, wv[q][1].p[1], acc[r][3]);
      }
    }
  }
}

// 4x8 variant for small-N convs
__device__ __forceinline__ void mm48g(u64 (&acc)[4][4],
    const float* __restrict__ L, const float* __restrict__ W,
    int i0, int c0, int k0, int K)
{
  const float* Lp = L + i0 * LDA + k0;
  const float* Wp = W + k0 * 128 + c0;
#pragma unroll 1
  for (int k = 0; k < K; k += 4) {
    V4 wv[4][2];
#pragma unroll
    for (int q = 0; q < 4; q++) {
      wv[q][0].f = __ldg(reinterpret_cast<const float4*>(Wp + (k + q) * 128));
      wv[q][1].f = __ldg(reinterpret_cast<const float4*>(Wp + (k + q) * 128 + 4));
    }
#pragma unroll
    for (int r = 0; r < 4; r++) {
      V4 lv; lv.f = *reinterpret_cast<const float4*>(Lp + r * LDA + k);
#pragma unroll
      for (int q = 0; q < 4; q++) {
        u64 lp = bcast2(lv.s[q]);
        acc[r][0] = ffma2(lp, wv[q][0].p[0], acc[r][0]);
        acc[r][1] = ffma2(lp, wv[q][0].p[1], acc[r][1]);
        acc[r][2] = ffma2(lp, wv[q][1].p[0], acc[r][2]);
        acc[r][3] = ffma2(lp, wv[q][1].p[1], acc[r][3]);
      }
    }
  }
}

template<int RI>
__device__ __forceinline__ void storeT(const u64 (&acc)[RI][4],
    float* O, int i0, int c0)
{
#pragma unroll
  for (int r = 0; r < RI; r++) {
    V4 a, b;
    a.p[0] = acc[r][0]; a.p[1] = acc[r][1];
    b.p[0] = acc[r][2]; b.p[1] = acc[r][3];
    *reinterpret_cast<float4*>(O + (i0 + r) * LDA + c0)     = a.f;
    *reinterpret_cast<float4*>(O + (i0 + r) * LDA + c0 + 4) = b.f;
  }
}

template<int RI, bool RELU>
__device__ __forceinline__ void combineT(const u64 (&acc)[RI][4],
    const float* __restrict__ P, float* __restrict__ O,
    int i0, int c0, const float* __restrict__ bias)
{
  float4 b1 = *reinterpret_cast<const float4*>(bias + c0);
  float4 b2 = *reinterpret_cast<const float4*>(bias + c0 + 4);
#pragma unroll
  for (int r = 0; r < RI; r++) {
    V4 a, b, o1, o2;
    a.p[0] = acc[r][0]; a.p[1] = acc[r][1];
    b.p[0] = acc[r][2]; b.p[1] = acc[r][3];
    o1.f = *reinterpret_cast<const float4*>(P + (i0 + r) * LDA + c0);
    o2.f = *reinterpret_cast<const float4*>(P + (i0 + r) * LDA + c0 + 4);
    a.f.x += o1.f.x + b1.x; a.f.y += o1.f.y + b1.y;
    a.f.z += o1.f.z + b1.z; a.f.w += o1.f.w + b1.w;
    b.f.x += o2.f.x + b2.x; b.f.y += o2.f.y + b2.y;
    b.f.z += o2.f.z + b2.z; b.f.w += o2.f.w + b2.w;
    if (RELU) {
      a.f.x = fmaxf(a.f.x, 0.f); a.f.y = fmaxf(a.f.y, 0.f);
      a.f.z = fmaxf(a.f.z, 0.f); a.f.w = fmaxf(a.f.w, 0.f);
      b.f.x = fmaxf(b.f.x, 0.f); b.f.y = fmaxf(b.f.y, 0.f);
      b.f.z = fmaxf(b.f.z, 0.f); b.f.w = fmaxf(b.f.w, 0.f);
    }
    *reinterpret_cast<float4*>(O + (i0 + r) * LDA + c0)     = a.f;
    *reinterpret_cast<float4*>(O + (i0 + r) * LDA + c0 + 4) = b.f;
  }
}

__device__ __forceinline__ float warp_red_sum(float v) {
#pragma unroll
  for (int o = 16; o; o >>= 1) v += __shfl_xor_sync(0xffffffffu, v, o);
  return v;
}

// ---------------------------------------------------------------------------
// conv, N=64: A = relu( (adj@A)/cnt @ Wr + A@Wroot + br )
// ---------------------------------------------------------------------------
__device__ void conv64(Smem* s, const float* __restrict__ wr_t,
    const float* __restrict__ wroot_t, const float* __restrict__ br)
{
  const int tid = threadIdx.x;
  // agg = (masks @ A)/cnt -> B : 4 rows x 8 cols per thread
  {
    const int i0 = (tid >> 4) * 4, c0 = (tid & 15) * 4;
    u64 m0 = s->masks[i0], m1 = s->masks[i0+1], m2 = s->masks[i0+2], m3 = s->masks[i0+3];
    u64 a[4][4];
#pragma unroll
    for (int r = 0; r < 4; r++)
#pragma unroll
      for (int j = 0; j < 4; j++) a[r][j] = 0ull;
    u64 mm = m0 | m1 | m2 | m3;
    const float* Ap = s->A + c0;
    while (mm) {
      int j = __ffsll((long long)mm) - 1;
      mm &= mm - 1;
      V4 ra, rb;
      ra.f = *reinterpret_cast<const float4*>(Ap + j * LDA);
      rb.f = *reinterpret_cast<const float4*>(Ap + j * LDA + 64);
      if ((m0 >> j) & 1) { a[0][0]=fadd2(a[0][0],ra.p[0]); a[0][1]=fadd2(a[0][1],ra.p[1]);
                           a[0][2]=fadd2(a[0][2],rb.p[0]); a[0][3]=fadd2(a[0][3],rb.p[1]); }
      if ((m1 >> j) & 1) { a[1][0]=fadd2(a[1][0],ra.p[0]); a[1][1]=fadd2(a[1][1],ra.p[1]);
                           a[1][2]=fadd2(a[1][2],rb.p[0]); a[1][3]=fadd2(a[1][3],rb.p[1]); }
      if ((m2 >> j) & 1) { a[2][0]=fadd2(a[2][0],ra.p[0]); a[2][1]=fadd2(a[2][1],ra.p[1]);
                           a[2][2]=fadd2(a[2][2],rb.p[0]); a[2][3]=fadd2(a[2][3],rb.p[1]); }
      if ((m3 >> j) & 1) { a[3][0]=fadd2(a[3][0],ra.p[0]); a[3][1]=fadd2(a[3][1],ra.p[1]);
                           a[3][2]=fadd2(a[3][2],rb.p[0]); a[3][3]=fadd2(a[3][3],rb.p[1]); }
    }
    u64 msk[4] = {m0, m1, m2, m3};
#pragma unroll
    for (int r = 0; r < 4; r++) {
      u64 rc = bcast2(1.f / fmaxf((float)__popcll(msk[r]), 1.f));
      V4 o;
      o.p[0] = fmul2(a[r][0], rc); o.p[1] = fmul2(a[r][1], rc);
      *reinterpret_cast<float4*>(s->B + (i0 + r) * LDA + c0) = o.f;
      o.p[0] = fmul2(a[r][2], rc); o.p[1] = fmul2(a[r][3], rc);
      *reinterpret_cast<float4*>(s->B + (i0 + r) * LDA + c0 + 64) = o.f;
    }
  }
  __syncthreads();

  const int grp = tid >> 7, t = tid & 127;
  const int i0 = (t >> 4) * 8, c0 = (t & 15) * 8;
  u64 acc[8][4];
#pragma unroll
  for (int r = 0; r < 8; r++)
#pragma unroll
    for (int j = 0; j < 4; j++) acc[r][j] = 0ull;
  if (grp == 0) mm88(acc, s->B, wr_t, i0, c0, 0, 128);
  else          mm88(acc, s->A, wroot_t, i0, c0, 0, 128);
  __syncthreads();
  if (grp == 1) storeT<8>(acc, s->B, i0, c0);
  __syncthreads();
  if (grp == 0) combineT<8, true>(acc, s->B, s->A, i0, c0, br);
  __syncthreads();
}

// ---------------------------------------------------------------------------
// conv, N<=16 (float adjP)
// ---------------------------------------------------------------------------
template<int NI>
__device__ void conv_small(Smem* s, const float* __restrict__ wr_t,
    const float* __restrict__ wroot_t, const float* __restrict__ br)
{
  const int tid = threadIdx.x;
  if (tid < NI * 16) {
    int row = tid >> 4, c0 = (tid & 15) * 4;
    float a[8] = {0,0,0,0,0,0,0,0};
    int cnt = 0;
    for (int j = 0; j < NI; j++) {
      float v = s->adjP[row * LDP + j];
      if (v != 0.f) {
        cnt++;
        V4 ra, rb;
        ra.f = *reinterpret_cast<const float4*>(s->A + j * LDA + c0);
        rb.f = *reinterpret_cast<const float4*>(s->A + j * LDA + c0 + 64);
        a[0]=fmaf(v,ra.s[0],a[0]); a[1]=fmaf(v,ra.s[1],a[1]);
        a[2]=fmaf(v,ra.s[2],a[2]); a[3]=fmaf(v,ra.s[3],a[3]);
        a[4]=fmaf(v,rb.s[0],a[4]); a[5]=fmaf(v,rb.s[1],a[5]);
        a[6]=fmaf(v,rb.s[2],a[6]); a[7]=fmaf(v,rb.s[3],a[7]);
      }
    }
    float rc = 1.f / fmaxf((float)cnt, 1.f);
    *reinterpret_cast<float4*>(s->B + row * LDA + c0) =
        make_float4(a[0]*rc, a[1]*rc, a[2]*rc, a[3]*rc);
    *reinterpret_cast<float4*>(s->B + row * LDA + c0 + 64) =
        make_float4(a[4]*rc, a[5]*rc, a[6]*rc, a[7]*rc);
  }
  __syncthreads();

  const int grp = tid >> 7, t = tid & 127;
  const int i0 = (t >> 4) * 4, c0 = (t & 15) * 8;
  const bool act = i0 < NI;
  u64 acc[4][4];
#pragma unroll
  for (int r = 0; r < 4; r++)
#pragma unroll
    for (int j = 0; j < 4; j++) acc[r][j] = 0ull;
  if (act) {
    if (grp == 0) mm48g(acc, s->B, wr_t, i0, c0, 0, 128);
    else          mm48g(acc, s->A, wroot_t, i0, c0, 0, 128);
  }
  __syncthreads();
  if (grp == 1 && act) storeT<4>(acc, s->B, i0, c0);
  __syncthreads();
  if (grp == 0 && act) combineT<4, true>(acc, s->B, s->A, i0, c0, br);
  __syncthreads();
}

// ---------------------------------------------------------------------------
// mean pool of A rows -> xsum[stage]
// ---------------------------------------------------------------------------
__device__ void mean_pool(Smem* s, int NI, int stage) {
  const int tid = threadIdx.x;
  int q = tid >> 7, h = tid & 127;
  float a = 0.f;
  for (int r = q; r < NI; r += 2) a += s->A[r * LDA + h];
  s->part[q * 128 + h] = a;
  __syncthreads();
  if (tid < 128)
    s->xsum[stage * 128 + tid] = (s->part[tid] + s->part[128 + tid]) * (1.f / (float)NI);
  __syncthreads();
}

// ---------------------------------------------------------------------------
// top-k (warp 0)
// ---------------------------------------------------------------------------
template<int KK>
__device__ void topk(Smem* s, int NI) {
  if (threadIdx.x < 32) {
    int lane = threadIdx.x;
    float v0 = (lane < NI) ? s->fit[lane] : -2.f;
    float v1 = (lane + 32 < NI) ? s->fit[lane + 32] : -2.f;
#pragma unroll 1
    for (int t = 0; t < KK; t++) {
      float bv; int bi;
      if (v0 >= v1) { bv = v0; bi = lane; } else { bv = v1; bi = lane + 32; }
#pragma unroll
      for (int o = 16; o; o >>= 1) {
        float ov = __shfl_xor_sync(0xffffffffu, bv, o);
        int   oi = __shfl_xor_sync(0xffffffffu, bi, o);
        if (ov > bv || (ov == bv && oi < bi)) { bv = ov; bi = oi; }
      }
      if (lane == 0) { s->perm[t] = bi; s->vals[t] = bv; }
      if (bi == lane) v0 = -2.f;
      if (bi == lane + 32) v1 = -2.f;
    }
  }
}

// ---------------------------------------------------------------------------
// ASAP pool 1 (N=64 -> 16, bitmask adjacency)
// ---------------------------------------------------------------------------
__device__ void pool1(Smem* s, const float* __restrict__ lw_t,
    const float* __restrict__ lb, const float* __restrict__ aw, float ab,
    const float* __restrict__ l1w, float l1b,
    const float* __restrict__ l2w,
    const float* __restrict__ l3w, float l3b)
{
  const int tid = threadIdx.x;
  const int w = tid >> 5, lane = tid & 31;

  if (tid < 64) s->masks[tid] |= (1ull << tid);
  __syncthreads();
  if (tid < 64) s->degw[tid] = (float)__popcll(s->masks[tid]);

  // masked max-agg -> B : 4 rows x 8 cols
  {
    const int i0 = (tid >> 4) * 4, c0 = (tid & 15) * 4;
    u64 msk[4] = {s->masks[i0], s->masks[i0+1], s->masks[i0+2], s->masks[i0+3]};
    float a[4][8];
#pragma unroll
    for (int r = 0; r < 4; r++)
#pragma unroll
      for (int c = 0; c < 8; c++) a[r][c] = -1e30f;
    u64 mm = msk[0] | msk[1] | msk[2] | msk[3];
    const float* Ap = s->A + c0;
    while (mm) {
      int j = __ffsll((long long)mm) - 1;
      mm &= mm - 1;
      V4 ra, rb;
      ra.f = *reinterpret_cast<const float4*>(Ap + j * LDA);
      rb.f = *reinterpret_cast<const float4*>(Ap + j * LDA + 64);
#pragma unroll
      for (int r = 0; r < 4; r++) {
        if ((msk[r] >> j) & 1) {
          a[r][0]=fmaxf(a[r][0],ra.s[0]); a[r][1]=fmaxf(a[r][1],ra.s[1]);
          a[r][2]=fmaxf(a[r][2],ra.s[2]); a[r][3]=fmaxf(a[r][3],ra.s[3]);
          a[r][4]=fmaxf(a[r][4],rb.s[0]); a[r][5]=fmaxf(a[r][5],rb.s[1]);
          a[r][6]=fmaxf(a[r][6],rb.s[2]); a[r][7]=fmaxf(a[r][7],rb.s[3]);
        }
      }
    }
#pragma unroll
    for (int r = 0; r < 4; r++) {
      *reinterpret_cast<float4*>(s->B + (i0+r)*LDA + c0) =
          make_float4(a[r][0], a[r][1], a[r][2], a[r][3]);
      *reinterpret_cast<float4*>(s->B + (i0+r)*LDA + c0 + 64) =
          make_float4(a[r][4], a[r][5], a[r][6], a[r][7]);
    }
  }
  __syncthreads();

  // XQ = B @ lw^T + lb -> B (K-split over the 2 groups)
  {
    const int grp = tid >> 7, t = tid & 127;
    const int i0 = (t >> 4) * 8, c0 = (t & 15) * 8;
    u64 acc[8][4];
#pragma unroll
    for (int r = 0; r < 8; r++)
#pragma unroll
      for (int j = 0; j < 4; j++) acc[r][j] = 0ull;
    mm88(acc, s->B, lw_t, i0, c0, grp ? 64 : 0, 64);
    __syncthreads();
    if (grp == 1) storeT<8>(acc, s->B, i0, c0);
    __syncthreads();
    if (grp == 0) combineT<8, false>(acc, s->B, s->B, i0, c0, lb);
  }
  __syncthreads();

  // s1 = XQ.aw[:128] (B), s2 = X.aw[128:] (A)
  for (int d = w; d < 128; d += 8) {
    const float* row = (d < 64) ? (s->B + d * LDA) : (s->A + (d - 64) * LDA);
    const float* wv = (d < 64) ? aw : (aw + 128);
    float4 a = reinterpret_cast<const float4*>(row)[lane];
    float4 b = reinterpret_cast<const float4*>(wv)[lane];
    float dot = warp_red_sum(a.x*b.x + a.y*b.y + a.z*b.z + a.w*b.w);
    if (lane == 0) { if (d < 64) s->s1[d] = dot; else s->s2[d - 64] = dot; }
  }
  __syncthreads();

  // masked softmax -> S
  for (int i = w; i < 64; i += 8) {
    u64 mi = s->masks[i];
    float s1i = s->s1[i];
    bool vA = (mi >> lane) & 1, vB = (mi >> (lane + 32)) & 1;
    float e0 = s1i + s->s2[lane] + ab;       e0 = (e0 > 0.f) ? e0 : SLOPE * e0;
    float e1 = s1i + s->s2[lane + 32] + ab;  e1 = (e1 > 0.f) ? e1 : SLOPE * e1;
    float ev0 = vA ? e0 : -1e30f, ev1 = vB ? e1 : -1e30f;
    float mx = fmaxf(ev0, ev1);
#pragma unroll
    for (int o = 16; o; o >>= 1) mx = fmaxf(mx, __shfl_xor_sync(0xffffffffu, mx, o));
    float ex0 = vA ? __expf(ev0 - mx) : 0.f;
    float ex1 = vB ? __expf(ev1 - mx) : 0.f;
    float sum = warp_red_sum(ex0 + ex1);
    float inv = 1.f / sum;
    s->S[i * LDS_ + lane]      = ex0 * inv;
    s->S[i * LDS_ + lane + 32] = ex1 * inv;
  }
  __syncthreads();

  // XC = S @ X -> B : 4 rows x 8 cols, zero-skip
  {
    const int i0 = (tid >> 4) * 4, c0 = (tid & 15) * 4;
    u64 a[4][4];
#pragma unroll
    for (int r = 0; r < 4; r++)
#pragma unroll
      for (int j = 0; j < 4; j++) a[r][j] = 0ull;
    for (int k = 0; k < 64; k++) {
      float l0 = s->S[i0*LDS_ + k], l1 = s->S[(i0+1)*LDS_ + k];
      float l2 = s->S[(i0+2)*LDS_ + k], l3 = s->S[(i0+3)*LDS_ + k];
      if (l0 == 0.f && l1 == 0.f && l2 == 0.f && l3 == 0.f) continue;
      V4 ra, rb;
      ra.f = *reinterpret_cast<const float4*>(s->A + k * LDA + c0);
      rb.f = *reinterpret_cast<const float4*>(s->A + k * LDA + c0 + 64);
      float lv[4] = {l0, l1, l2, l3};
#pragma unroll
      for (int r = 0; r < 4; r++) {
        if (lv[r] != 0.f) {
          u64 lp = bcast2(lv[r]);
          a[r][0]=ffma2(lp,ra.p[0],a[r][0]); a[r][1]=ffma2(lp,ra.p[1],a[r][1]);
          a[r][2]=ffma2(lp,rb.p[0],a[r][2]); a[r][3]=ffma2(lp,rb.p[1],a[r][3]);
        }
      }
    }
#pragma unroll
    for (int r = 0; r < 4; r++) {
      V4 o;
      o.p[0]=a[r][0]; o.p[1]=a[r][1];
      *reinterpret_cast<float4*>(s->B + (i0+r)*LDA + c0) = o.f;
      o.p[0]=a[r][2]; o.p[1]=a[r][3];
      *reinterpret_cast<float4*>(s->B + (i0+r)*LDA + c0 + 64) = o.f;
    }
  }
  __syncthreads();

  // av/bv/cv dots
  for (int d = w; d < 192; d += 8) {
    int grp = d >> 6, i = d & 63;
    const float* wv = (grp == 0) ? l1w : (grp == 1) ? l2w : l3w;
    float4 a = reinterpret_cast<const float4*>(s->B + i * LDA)[lane];
    float4 b = reinterpret_cast<const float4*>(wv)[lane];
    float dot = warp_red_sum(a.x*b.x + a.y*b.y + a.z*b.z + a.w*b.w);
    if (lane == 0) {
      if (grp == 0)      s->av[i] = dot + l1b;
      else if (grp == 1) s->bv[i] = dot;
      else               s->cv[i] = dot + l3b;
    }
  }
  __syncthreads();

  if (tid < 64) {
    u64 mm = s->masks[tid];
    float a = 0.f;
    while (mm) {
      int j = __ffsll((long long)mm) - 1;
      mm &= mm - 1;
      a += s->av[j];
    }
    float f = a - s->bv[tid] * s->degw[tid] + s->cv[tid];
    s->fit[tid] = 1.f / (1.f + expf(-f));
  }
  __syncthreads();
  topk<16>(s, 64);
  __syncthreads();

  // XN = XC[perm]*vals -> A rows 0..15 ; T = S[perm]@adj1 -> A rows 16..31
  for (int idx = tid; idx < 16 * 128; idx += THREADS) {
    int t2 = idx >> 7, h = idx & 127;
    s->A[t2 * LDA + h] = s->B[s->perm[t2] * LDA + h] * s->vals[t2];
  }
  for (int idx = tid; idx < 16 * 64; idx += THREADS) {
    int t2 = idx >> 6, m = idx & 63;
    const float* srow = s->S + s->perm[t2] * LDS_;
    float a = 0.f;
    for (int n = 0; n < 64; n++) {
      float sv = srow[n];
      if (sv != 0.f && ((s->masks[n] >> m) & 1)) a += sv;
    }
    s->A[(16 + t2) * LDA + m] = a;
  }
  __syncthreads();

  // adjn = T @ S[perm]^T, zero diag -> adjP
  {
    int t2 = tid >> 4, l = tid & 15;
    const float* sl = s->S + s->perm[l] * LDS_;
    const float* tr = s->A + (16 + t2) * LDA;
    float a = 0.f;
    for (int m = 0; m < 64; m++) a += tr[m] * sl[m];
    s->adjP[t2 * LDP + l] = (t2 == l) ? 0.f : a;
  }
  __syncthreads();
}

// ---------------------------------------------------------------------------
// ASAP pool 2 (N=16 -> 4, float adjP)
// ---------------------------------------------------------------------------
__device__ void pool2(Smem* s, const float* __restrict__ lw_t,
    const float* __restrict__ lb, const float* __restrict__ aw, float ab,
    const float* __restrict__ l1w, float l1b,
    const float* __restrict__ l2w,
    const float* __restrict__ l3w, float l3b)
{
  const int tid = threadIdx.x;
  const int w = tid >> 5, lane = tid & 31;

  if (tid < 16) {
    float d = s->adjP[tid * LDP + tid];
    if (d == 0.f) s->adjP[tid * LDP + tid] = 1.f;
  }
  __syncthreads();
  if (tid < 16) {
    float sum = 0.f;
    for (int j = 0; j < 16; j++) sum += s->adjP[tid * LDP + j];
    s->degw[tid] = sum;
  }

  // masked max-agg -> B
  {
    int row = tid >> 4, c0 = (tid & 15) * 4;
    float a[8];
#pragma unroll
    for (int c = 0; c < 8; c++) a[c] = -1e30f;
    for (int j = 0; j < 16; j++) {
      if (s->adjP[row * LDP + j] != 0.f) {
        V4 ra, rb;
        ra.f = *reinterpret_cast<const float4*>(s->A + j * LDA + c0);
        rb.f = *reinterpret_cast<const float4*>(s->A + j * LDA + c0 + 64);
        a[0]=fmaxf(a[0],ra.s[0]); a[1]=fmaxf(a[1],ra.s[1]);
        a[2]=fmaxf(a[2],ra.s[2]); a[3]=fmaxf(a[3],ra.s[3]);
        a[4]=fmaxf(a[4],rb.s[0]); a[5]=fmaxf(a[5],rb.s[1]);
        a[6]=fmaxf(a[6],rb.s[2]); a[7]=fmaxf(a[7],rb.s[3]);
      }
    }
    *reinterpret_cast<float4*>(s->B + row*LDA + c0) = make_float4(a[0],a[1],a[2],a[3]);
    *reinterpret_cast<float4*>(s->B + row*LDA + c0 + 64) = make_float4(a[4],a[5],a[6],a[7]);
  }
  __syncthreads();

  // XQ = B @ lw^T + lb -> B (K-split, 16 rows, 4-row tiles)
  {
    const int grp = tid >> 7, t = tid & 127;
    const int i0 = (t >> 4) * 4, c0 = (t & 15) * 8;
    const bool act = i0 < 16;
    u64 acc[4][4];
#pragma unroll
    for (int r = 0; r < 4; r++)
#pragma unroll
      for (int j = 0; j < 4; j++) acc[r][j] = 0ull;
    if (act) mm48g(acc, s->B, lw_t, i0, c0, grp ? 64 : 0, 64);
    __syncthreads();
    if (grp == 1 && act) storeT<4>(acc, s->B, i0, c0);
    __syncthreads();
    if (grp == 0 && act) combineT<4, false>(acc, s->B, s->B, i0, c0, lb);
  }
  __syncthreads();

  // s1/s2
  for (int d = w; d < 32; d += 8) {
    const float* row = (d < 16) ? (s->B + d * LDA) : (s->A + (d - 16) * LDA);
    const float* wv = (d < 16) ? aw : (aw + 128);
    float4 a = reinterpret_cast<const float4*>(row)[lane];
    float4 b = reinterpret_cast<const float4*>(wv)[lane];
    float dot = warp_red_sum(a.x*b.x + a.y*b.y + a.z*b.z + a.w*b.w);
    if (lane == 0) { if (d < 16) s->s1[d] = dot; else s->s2[d - 16] = dot; }
  }
  __syncthreads();

  // attention (warp per row, rows 0..15, two passes)
  for (int i = w; i < 16; i += 8) {
    float adjv = (lane < 16) ? s->adjP[i * LDP + lane] : 0.f;
    float e = s->s1[i] + ((lane < 16) ? s->s2[lane] : 0.f) + ab;
    e = (e > 0.f) ? e : SLOPE * e;
    float ev = (adjv != 0.f) ? e : -1e30f;
    float mx = ev;
#pragma unroll
    for (int o = 16; o; o >>= 1) mx = fmaxf(mx, __shfl_xor_sync(0xffffffffu, mx, o));
    float ex = (adjv != 0.f) ? __expf(ev - mx) : 0.f;
    float sum = warp_red_sum(ex);
    if (lane < 16) s->S[i * LDS_ + lane] = ex / sum;
  }
  __syncthreads();

  // XC = S @ X -> B
  {
    int row = tid >> 4, c0 = (tid & 15) * 4;
    float a[8] = {0,0,0,0,0,0,0,0};
    for (int j = 0; j < 16; j++) {
      float sv = s->S[row * LDS_ + j];
      if (sv != 0.f) {
        V4 ra, rb;
        ra.f = *reinterpret_cast<const float4*>(s->A + j * LDA + c0);
        rb.f = *reinterpret_cast<const float4*>(s->A + j * LDA + c0 + 64);
        a[0]=fmaf(sv,ra.s[0],a[0]); a[1]=fmaf(sv,ra.s[1],a[1]);
        a[2]=fmaf(sv,ra.s[2],a[2]); a[3]=fmaf(sv,ra.s[3],a[3]);
        a[4]=fmaf(sv,rb.s[0],a[4]); a[5]=fmaf(sv,rb.s[1],a[5]);
        a[6]=fmaf(sv,rb.s[2],a[6]); a[7]=fmaf(sv,rb.s[3],a[7]);
      }
    }
    *reinterpret_cast<float4*>(s->B + row*LDA + c0) = make_float4(a[0],a[1],a[2],a[3]);
    *reinterpret_cast<float4*>(s->B + row*LDA + c0 + 64) = make_float4(a[4],a[5],a[6],a[7]);
  }
  __syncthreads();

  // av/bv/cv
  for (int d = w; d < 48; d += 8) {
    int grp = d >> 4, i = d & 15;
    const float* wv = (grp == 0) ? l1w : (grp == 1) ? l2w : l3w;
    float4 a = reinterpret_cast<const float4*>(s->B + i * LDA)[lane];
    float4 b = reinterpret_cast<const float4*>(wv)[lane];
    float dot = warp_red_sum(a.x*b.x + a.y*b.y + a.z*b.z + a.w*b.w);
    if (lane == 0) {
      if (grp == 0)      s->av[i] = dot + l1b;
      else if (grp == 1) s->bv[i] = dot;
      else               s->cv[i] = dot + l3b;
    }
  }
  __syncthreads();

  if (tid < 16) {
    float a = 0.f;
    for (int j = 0; j < 16; j++) a += s->adjP[tid * LDP + j] * s->av[j];
    float f = a - s->bv[tid] * s->degw[tid] + s->cv[tid];
    s->fit[tid] = 1.f / (1.f + expf(-f));
  }
  __syncthreads();
  topk<4>(s, 16);
  __syncthreads();

  // XN = XC[perm]*vals -> A rows 0..3  (FIXED: strided loop covers all 4 rows)
  for (int idx = tid; idx < 4 * 128; idx += THREADS) {
    int t2 = idx >> 7, h = idx & 127;
    s->A[t2 * LDA + h] = s->B[s->perm[t2] * LDA + h] * s->vals[t2];
  }
  // T = S[perm] @ adjP -> A rows 16..19
  if (tid < 64) {
    int t2 = tid >> 4, m = tid & 15;
    const float* srow = s->S + s->perm[t2] * LDS_;
    float a = 0.f;
    for (int n = 0; n < 16; n++) a += srow[n] * s->adjP[n * LDP + m];
    s->A[(16 + t2) * LDA + m] = a;
  }
  __syncthreads();
  if (tid < 16) {
    int t2 = tid >> 2, l = tid & 3;
    const float* sl = s->S + s->perm[l] * LDS_;
    const float* tr = s->A + (16 + t2) * LDA;
    float a = 0.f;
    for (int m = 0; m < 16; m++) a += tr[m] * sl[m];
    s->adjP[t2 * LDP + l] = (t2 == l) ? 0.f : a;
  }
  __syncthreads();
}

// ---------------------------------------------------------------------------
// main kernel
// ---------------------------------------------------------------------------
__global__ void __launch_bounds__(THREADS, 2) asap_kernel(
    const float* __restrict__ x,          const float* __restrict__ adj,
    const float* __restrict__ conv1_br,
    const float* __restrict__ convs_br,
    const float* __restrict__ pool_lin_b,
    const float* __restrict__ pool_att_w, const float* __restrict__ pool_att_b,
    const float* __restrict__ pool_le1_w, const float* __restrict__ pool_le1_b,
    const float* __restrict__ pool_le2_w,
    const float* __restrict__ pool_le3_w, const float* __restrict__ pool_le3_b,
    const float* __restrict__ lin1_w,     const float* __restrict__ lin1_b,
    const float* __restrict__ lin2_w,     const float* __restrict__ lin2_b,
    float* __restrict__ out)
{
  extern __shared__ unsigned char smraw[];
  Smem* s = reinterpret_cast<Smem*>(smraw);
  const int g = blockIdx.x, tid = threadIdx.x;
  const int w = tid >> 5, lane = tid & 31;

  // load features + binary adjacency -> masks
  {
    const float4* xs = reinterpret_cast<const float4*>(x + (size_t)g * 8192);
#pragma unroll
    for (int i = 0; i < 8; i++) {
      int idx = tid + i * 256;
      int row = idx >> 5, c = (idx & 31) * 4;
      *reinterpret_cast<float4*>(s->A + row * LDA + c) = xs[idx];
    }
    if (tid < 64) {
      const float4* ar = reinterpret_cast<const float4*>(adj + (size_t)g * 4096 + tid * 64);
      u64 m = 0;
#pragma unroll
      for (int c = 0; c < 16; c++) {
        float4 v = __ldg(ar + c);
        if (v.x != 0.f) m |= 1ull << (c * 4 + 0);
        if (v.y != 0.f) m |= 1ull << (c * 4 + 1);
        if (v.z != 0.f) m |= 1ull << (c * 4 + 2);
        if (v.w != 0.f) m |= 1ull << (c * 4 + 3);
      }
      s->masks[tid] = m;
    }
  }
  __syncthreads();

  const float* W = g_WT;
  conv64(s, W + 0*16384, W + 1*16384, conv1_br);
  mean_pool(s, 64, 0);

  conv64(s, W + 2*16384, W + 6*16384, convs_br);
  mean_pool(s, 64, 1);

  pool1(s, W + 10*16384, pool_lin_b, pool_att_w, pool_att_b[0],
        pool_le1_w, pool_le1_b[0], pool_le2_w, pool_le3_w, pool_le3_b[0]);

  conv_small<16>(s, W + 3*16384, W + 7*16384, convs_br + 128);
  mean_pool(s, 16, 2);

  conv_small<16>(s, W + 4*16384, W + 8*16384, convs_br + 256);
  mean_pool(s, 16, 3);

  pool2(s, W + 11*16384, pool_lin_b + 128, pool_att_w + 256, pool_att_b[1],
        pool_le1_w + 128, pool_le1_b[1], pool_le2_w + 128,
        pool_le3_w + 128, pool_le3_b[1]);

  conv_small<4>(s, W + 5*16384, W + 9*16384, convs_br + 384);
  mean_pool(s, 4, 4);

  // MLP head
  for (int d = w; d < 128; d += 8) {
    const float4* zr = reinterpret_cast<const float4*>(s->xsum);
    const float4* wr = reinterpret_cast<const float4*>(lin1_w + d * 640);
    float a = 0.f;
#pragma unroll
    for (int c = 0; c < 5; c++) {
      float4 zc = zr[lane + 32 * c];
      float4 wc = __ldg(wr + lane + 32 * c);
      a += zc.x*wc.x + zc.y*wc.y + zc.z*wc.z + zc.w*wc.w;
    }
    a = warp_red_sum(a);
    if (lane == 0) s->zz[d] = fmaxf(a + lin1_b[d], 0.f);
  }
  __syncthreads();
  for (int d = w; d < 10; d += 8) {
    float4 zc = reinterpret_cast<const float4*>(s->zz)[lane];
    float4 wc = __ldg(reinterpret_cast<const float4*>(lin2_w + d * 128) + lane);
    float a = warp_red_sum(zc.x*wc.x + zc.y*wc.y + zc.z*wc.z + zc.w*wc.w);
    if (lane == 0) s->yy[d] = a + lin2_b[d];
  }
  __syncthreads();
  if (tid == 0) {
    float mx = -1e30f;
    for (int c = 0; c < 10; c++) mx = fmaxf(mx, s->yy[c]);
    float sum = 0.f;
    for (int c = 0; c < 10; c++) sum += expf(s->yy[c] - mx);
    s->lse = mx + logf(sum);
  }
  __syncthreads();
  if (tid < 10) out[g * 10 + tid] = s->yy[tid] - s->lse;
}

// ---------------------------------------------------------------------------
// prologue: transpose the 12 [128x128] weight matrices into g_WT
// ---------------------------------------------------------------------------
__global__ void transpose_k(
    const float* __restrict__ conv1_wr, const float* __restrict__ conv1_wroot,
    const float* __restrict__ convs_wr, const float* __restrict__ convs_wroot,
    const float* __restrict__ pool_lin_w)
{
  __shared__ float t[32][33];
  int mat = blockIdx.y;
  int tile = blockIdx.x;
  int tx = tile & 3, ty = tile >> 2;
  const float* src =
      (mat == 0) ? conv1_wr :
      (mat == 1) ? conv1_wroot :
      (mat < 6)  ? convs_wr + (mat - 2) * 16384 :
      (mat < 10) ? convs_wroot + (mat - 6) * 16384 :
                   pool_lin_w + (mat - 10) * 16384;
#pragma unroll
  for (int r = threadIdx.y; r < 32; r += 8)
    t[r][threadIdx.x] = src[(ty * 32 + r) * 128 + tx * 32 + threadIdx.x];
  __syncthreads();
#pragma unroll
  for (int r = threadIdx.y; r < 32; r += 8)
    g_WT[mat * 16384 + (tx * 32 + r) * 128 + ty * 32 + threadIdx.x] = t[threadIdx.x][r];
}

// ---------------------------------------------------------------------------
// launch
// ---------------------------------------------------------------------------
extern "C" void kernel_launch(void* const* d_in, const int* in_sizes, int n_in,
                              void* d_out, int out_size)
{
  const float* x           = (const float*)d_in[0];
  const float* adj         = (const float*)d_in[1];
  const float* conv1_wr    = (const float*)d_in[2];
  const float* conv1_br    = (const float*)d_in[3];
  const float* conv1_wroot = (const float*)d_in[4];
  const float* convs_wr    = (const float*)d_in[5];
  const float* convs_br    = (const float*)d_in[6];
  const float* convs_wroot = (const float*)d_in[7];
  const float* pool_lin_w  = (const float*)d_in[8];
  const float* pool_lin_b  = (const float*)d_in[9];
  const float* pool_att_w  = (const float*)d_in[10];
  const float* pool_att_b  = (const float*)d_in[11];
  const float* pool_le1_w  = (const float*)d_in[12];
  const float* pool_le1_b  = (const float*)d_in[13];
  const float* pool_le2_w  = (const float*)d_in[14];
  const float* pool_le3_w  = (const float*)d_in[15];
  const float* pool_le3_b  = (const float*)d_in[16];
  const float* lin1_w      = (const float*)d_in[17];
  const float* lin1_b      = (const float*)d_in[18];
  const float* lin2_w      = (const float*)d_in[19];
  const float* lin2_b      = (const float*)d_in[20];
  float* out = (float*)d_out;

  transpose_k<<<dim3(16, 12), dim3(32, 8)>>>(
      conv1_wr, conv1_wroot, convs_wr, convs_wroot, pool_lin_w);

  cudaFuncSetAttribute(asap_kernel, cudaFuncAttributeMaxDynamicSharedMemorySize,
                       (int)sizeof(Smem));
  asap_kernel<<<G_TOT, THREADS, sizeof(Smem)>>>(
      x, adj, conv1_br, convs_br,
      pool_lin_b, pool_att_w, pool_att_b,
      pool_le1_w, pool_le1_b, pool_le2_w, pool_le3_w, pool_le3_b,
      lin1_w, lin1_b, lin2_w, lin2_b, out);
}